// round 1
// baseline (speedup 1.0000x reference)
#include <cuda_runtime.h>
#include <math.h>

#define BB   256
#define TT   256
#define DD   384
#define HH   64
#define MTOT (BB*TT)                       // 65536 rows
#define HEADELEMS ((size_t)MTOT*HH)        // 4194304 elems per tensor

// scratch for q,k,v  (3 * 16.8 MB fp32). __device__ global = allowed scratch.
__device__ float g_qkv[3 * (size_t)MTOT * HH];

// ---------------------------------------------------------------------------
// Projection: qkv[sel] = x @ W[sel],  M=65536, N=64, K=384
// BM=128, BN=64, BK=16, 256 threads, 8x4 micro-tile per thread
// ---------------------------------------------------------------------------
__global__ void __launch_bounds__(256, 2) proj_kernel(
    const float* __restrict__ x,
    const float* __restrict__ Wq,
    const float* __restrict__ Wk,
    const float* __restrict__ Wv)
{
    __shared__ __align__(16) float As[16][132];   // transposed x tile (pad=4)
    __shared__ __align__(16) float Bs[16][64];    // W tile

    const int m0  = blockIdx.x * 128;
    const int sel = blockIdx.y;
    const float* W = (sel == 0) ? Wq : (sel == 1) ? Wk : Wv;
    float* outp = g_qkv + (size_t)sel * HEADELEMS;

    const int tid = threadIdx.x;
    const int tx  = tid & 15;      // 0..15 -> 4-col group
    const int ty  = tid >> 4;      // 0..15 -> 8-row group

    float acc[8][4];
    #pragma unroll
    for (int i = 0; i < 8; ++i)
        #pragma unroll
        for (int j = 0; j < 4; ++j) acc[i][j] = 0.f;

    for (int k0 = 0; k0 < DD; k0 += 16) {
        // x tile: 128 rows x 16 cols, coalesced float4, store transposed
        #pragma unroll
        for (int it = 0; it < 2; ++it) {
            int idx = tid + it * 256;          // 0..511
            int r   = idx >> 2;                // 0..127
            int c   = (idx & 3) * 4;           // 0,4,8,12
            float4 v = *(const float4*)(x + (size_t)(m0 + r) * DD + k0 + c);
            As[c + 0][r] = v.x;
            As[c + 1][r] = v.y;
            As[c + 2][r] = v.z;
            As[c + 3][r] = v.w;
        }
        // W tile: 16 x 64, one float4 per thread
        {
            int r = tid >> 4;
            int c = (tid & 15) * 4;
            *(float4*)&Bs[r][c] = *(const float4*)(W + (size_t)(k0 + r) * HH + c);
        }
        __syncthreads();

        #pragma unroll
        for (int k = 0; k < 16; ++k) {
            float a[8], bb[4];
            *(float4*)&a[0] = *(const float4*)&As[k][ty * 8];
            *(float4*)&a[4] = *(const float4*)&As[k][ty * 8 + 4];
            *(float4*)&bb[0] = *(const float4*)&Bs[k][tx * 4];
            #pragma unroll
            for (int i = 0; i < 8; ++i)
                #pragma unroll
                for (int j = 0; j < 4; ++j)
                    acc[i][j] = fmaf(a[i], bb[j], acc[i][j]);
        }
        __syncthreads();
    }

    #pragma unroll
    for (int i = 0; i < 8; ++i)
        *(float4*)(outp + (size_t)(m0 + ty * 8 + i) * HH + tx * 4) =
            make_float4(acc[i][0], acc[i][1], acc[i][2], acc[i][3]);
}

// ---------------------------------------------------------------------------
// Attention: one CTA per batch, one thread per query row.
// q and o in registers; K/V tiles (64 rows) in smem; broadcast LDS reads.
// Online softmax with chunk-of-8 rescaling.
// ---------------------------------------------------------------------------
__global__ void __launch_bounds__(256, 1) attn_kernel(float* __restrict__ out)
{
    __shared__ __align__(16) float Ks[64][64];
    __shared__ __align__(16) float Vs[64][64];

    const int b = blockIdx.x;
    const int t = threadIdx.x;

    const float* qb = g_qkv + (size_t)b * TT * HH;
    const float* kb = g_qkv + HEADELEMS + (size_t)b * TT * HH;
    const float* vb = g_qkv + 2 * HEADELEMS + (size_t)b * TT * HH;

    // q row, pre-scaled by 1/sqrt(H) = 0.125
    float q[HH];
    {
        const float4* qr = (const float4*)(qb + (size_t)t * HH);
        #pragma unroll
        for (int j = 0; j < HH / 4; ++j) {
            float4 v = qr[j];
            q[4 * j + 0] = v.x * 0.125f;
            q[4 * j + 1] = v.y * 0.125f;
            q[4 * j + 2] = v.z * 0.125f;
            q[4 * j + 3] = v.w * 0.125f;
        }
    }

    float o[HH];
    #pragma unroll
    for (int j = 0; j < HH; ++j) o[j] = 0.f;
    float m = -1e30f;
    float l = 0.f;

    const int warp_tmax = t | 31;

    #pragma unroll 1
    for (int s0 = 0; s0 < TT; s0 += 64) {
        // cooperative tile load: 64x64 K and V, coalesced float4
        #pragma unroll
        for (int it = 0; it < 4; ++it) {
            int idx = t + it * 256;            // 0..1023
            int r   = idx >> 4;                // 0..63
            int c   = (idx & 15) * 4;          // 0..60
            *(float4*)&Ks[r][c] = *(const float4*)(kb + (size_t)(s0 + r) * HH + c);
            *(float4*)&Vs[r][c] = *(const float4*)(vb + (size_t)(s0 + r) * HH + c);
        }
        __syncthreads();

        if (warp_tmax >= s0) {                 // warp-level causal skip
            #pragma unroll 1
            for (int c0 = 0; c0 < 64; c0 += 8) {
                const int sbase = s0 + c0;
                if (t >= sbase) {              // thread-level causal skip
                    float sc[8];
                    #pragma unroll
                    for (int si = 0; si < 8; ++si) {
                        const float4* kr = (const float4*)&Ks[c0 + si][0];
                        float d0 = 0.f, d1 = 0.f, d2 = 0.f, d3 = 0.f;
                        #pragma unroll
                        for (int j = 0; j < 16; ++j) {
                            float4 kv = kr[j];
                            d0 = fmaf(q[4 * j + 0], kv.x, d0);
                            d1 = fmaf(q[4 * j + 1], kv.y, d1);
                            d2 = fmaf(q[4 * j + 2], kv.z, d2);
                            d3 = fmaf(q[4 * j + 3], kv.w, d3);
                        }
                        float d = (d0 + d1) + (d2 + d3);
                        sc[si] = (sbase + si <= t) ? d : -1e30f;
                    }
                    float cmax = sc[0];
                    #pragma unroll
                    for (int si = 1; si < 8; ++si) cmax = fmaxf(cmax, sc[si]);
                    float nm   = fmaxf(m, cmax);
                    float corr = __expf(m - nm);
                    m = nm;
                    l *= corr;
                    #pragma unroll
                    for (int j = 0; j < HH; ++j) o[j] *= corr;
                    #pragma unroll
                    for (int si = 0; si < 8; ++si) {
                        float p = __expf(sc[si] - nm);
                        l += p;
                        const float4* vr = (const float4*)&Vs[c0 + si][0];
                        #pragma unroll
                        for (int j = 0; j < 16; ++j) {
                            float4 vv = vr[j];
                            o[4 * j + 0] = fmaf(p, vv.x, o[4 * j + 0]);
                            o[4 * j + 1] = fmaf(p, vv.y, o[4 * j + 1]);
                            o[4 * j + 2] = fmaf(p, vv.z, o[4 * j + 2]);
                            o[4 * j + 3] = fmaf(p, vv.w, o[4 * j + 3]);
                        }
                    }
                }
            }
        }
        __syncthreads();
    }

    const float inv = 1.f / l;
    float4* orow = (float4*)(out + ((size_t)b * TT + t) * HH);
    #pragma unroll
    for (int j = 0; j < 16; ++j)
        orow[j] = make_float4(o[4 * j + 0] * inv, o[4 * j + 1] * inv,
                              o[4 * j + 2] * inv, o[4 * j + 3] * inv);
}

// ---------------------------------------------------------------------------
extern "C" void kernel_launch(void* const* d_in, const int* in_sizes, int n_in,
                              void* d_out, int out_size)
{
    const float* x  = (const float*)d_in[0];
    const float* Wq = (const float*)d_in[1];
    const float* Wk = (const float*)d_in[2];
    const float* Wv = (const float*)d_in[3];
    float* out = (float*)d_out;

    dim3 pgrid(MTOT / 128, 3);
    proj_kernel<<<pgrid, 256>>>(x, Wq, Wk, Wv);
    attn_kernel<<<BB, 256>>>(out);
}

// round 3
// speedup vs baseline: 1.4476x; 1.4476x over previous
#include <cuda_runtime.h>
#include <cuda_bf16.h>
#include <math.h>
#include <stdint.h>

#define BB   256
#define TT   256
#define DD   384
#define HH   64
#define MTOT (BB*TT)                       // 65536 rows
#define HEADELEMS ((size_t)MTOT*HH)

// scratch: q,k,v fp32 (50 MB) + split weights (transposed [n][k], bf16)
__device__ float g_qkv[3 * (size_t)MTOT * HH];
__device__ __nv_bfloat16 g_wh[192 * 384];
__device__ __nv_bfloat16 g_wl[192 * 384];

// ---------------------------------------------------------------------------
__device__ __forceinline__ uint32_t smem_u32(const void* p) {
    uint32_t a;
    asm("{ .reg .u64 t; cvta.to.shared.u64 t, %1; cvt.u32.u64 %0, t; }"
        : "=r"(a) : "l"(p));
    return a;
}

__device__ __forceinline__ void ldsm4(uint32_t r[4], uint32_t addr) {
    asm volatile("ldmatrix.sync.aligned.m8n8.x4.shared.b16 {%0,%1,%2,%3}, [%4];"
                 : "=r"(r[0]), "=r"(r[1]), "=r"(r[2]), "=r"(r[3]) : "r"(addr));
}

__device__ __forceinline__ void mma16816(float c[4], const uint32_t a[4],
                                         uint32_t b0, uint32_t b1) {
    asm volatile(
        "mma.sync.aligned.m16n8k16.row.col.f32.bf16.bf16.f32 "
        "{%0,%1,%2,%3}, {%4,%5,%6,%7}, {%8,%9}, {%0,%1,%2,%3};"
        : "+f"(c[0]), "+f"(c[1]), "+f"(c[2]), "+f"(c[3])
        : "r"(a[0]), "r"(a[1]), "r"(a[2]), "r"(a[3]), "r"(b0), "r"(b1));
}

// ---------------------------------------------------------------------------
// Weight split prep: g_wh/g_wl[n][k] = bf16 hi/lo of W(k, n), n in 0..191
// ---------------------------------------------------------------------------
__global__ void wsplit_kernel(const float* __restrict__ Wq,
                              const float* __restrict__ Wk,
                              const float* __restrict__ Wv) {
    int i = blockIdx.x * 256 + threadIdx.x;
    if (i >= 192 * 384) return;
    int n = i / 384;
    int k = i % 384;
    const float* W = (n < 64) ? Wq : (n < 128) ? Wk : Wv;
    float v = W[(size_t)k * HH + (n & 63)];
    __nv_bfloat16 h = __float2bfloat16(v);
    float lo = v - __bfloat162float(h);
    g_wh[i] = h;
    g_wl[i] = __float2bfloat16(lo);
}

// ---------------------------------------------------------------------------
// mma.sync projection: D[128 x 192] = x_tile @ [Wq|Wk|Wv], split-bf16 (3 prod)
// 512 threads, 16 warps (4m x 4n), warp tile 32x48, K chunks of 32.
// Smem row stride 40 halves (80B) -> conflict-free ldmatrix phases.
// ---------------------------------------------------------------------------
#define KC  32
#define KS  40
#define A_H 0
#define A_L 5120
#define B_H 10240
#define B_L 17920
#define PROJ_SMEM (25600 * 2)   // 51200 bytes

__global__ void __launch_bounds__(512, 1) proj_mma_kernel(const float* __restrict__ x)
{
    extern __shared__ __nv_bfloat16 sm[];
    const uint32_t sb = smem_u32(sm);
    const int tid  = threadIdx.x;
    const int lane = tid & 31;
    const int wid  = tid >> 5;
    const int wm   = wid & 3;        // m block: 32 rows
    const int wn   = wid >> 2;       // n block: 48 cols
    const int m0   = blockIdx.x * 128;

    // ldmatrix per-lane address components
    const int aRow = (lane & 7) + ((lane >> 3) & 1) * 8;   // 0..15
    const int aCol = ((lane >> 4) & 1) * 8;                // 0/8 (k)
    const int bN   = (lane & 7) + ((lane >> 4) & 1) * 8;   // 0..15 (n)
    const int bK   = ((lane >> 3) & 1) * 8;                // 0/8 (k)

    float c[2][6][4];
    #pragma unroll
    for (int mt = 0; mt < 2; ++mt)
        #pragma unroll
        for (int nt = 0; nt < 6; ++nt)
            #pragma unroll
            for (int j = 0; j < 4; ++j) c[mt][nt][j] = 0.f;

    #pragma unroll 1
    for (int ch = 0; ch < 12; ++ch) {
        const int k0 = ch * KC;
        if (ch) __syncthreads();

        // ---- A: 128 x 32 fp32 -> hi/lo bf16 (padded, per-row stride 40)
        #pragma unroll
        for (int it = 0; it < 2; ++it) {
            int idx = tid + it * 512;            // 0..1023 float4s
            int r   = idx >> 3;                  // 0..127
            int c4  = (idx & 7) * 4;             // 0..28
            float4 v = *(const float4*)(x + (size_t)(m0 + r) * DD + k0 + c4);
            __nv_bfloat16 h0 = __float2bfloat16(v.x);
            __nv_bfloat16 h1 = __float2bfloat16(v.y);
            __nv_bfloat16 h2 = __float2bfloat16(v.z);
            __nv_bfloat16 h3 = __float2bfloat16(v.w);
            __nv_bfloat16 l0 = __float2bfloat16(v.x - __bfloat162float(h0));
            __nv_bfloat16 l1 = __float2bfloat16(v.y - __bfloat162float(h1));
            __nv_bfloat16 l2 = __float2bfloat16(v.z - __bfloat162float(h2));
            __nv_bfloat16 l3 = __float2bfloat16(v.w - __bfloat162float(h3));
            uint32_t hp0 = ((uint32_t)__bfloat16_as_ushort(h1) << 16) | __bfloat16_as_ushort(h0);
            uint32_t hp1 = ((uint32_t)__bfloat16_as_ushort(h3) << 16) | __bfloat16_as_ushort(h2);
            uint32_t lp0 = ((uint32_t)__bfloat16_as_ushort(l1) << 16) | __bfloat16_as_ushort(l0);
            uint32_t lp1 = ((uint32_t)__bfloat16_as_ushort(l3) << 16) | __bfloat16_as_ushort(l2);
            int off = r * KS + c4;
            *(uint2*)(sm + A_H + off) = make_uint2(hp0, hp1);
            *(uint2*)(sm + A_L + off) = make_uint2(lp0, lp1);
        }

        // ---- B: 192 x 32 bf16 hi/lo
        #pragma unroll
        for (int it = 0; it < 2; ++it) {
            int idx = tid + it * 512;            // over 768 uint4 per array
            if (idx < 768) {
                int n  = idx >> 2;               // 0..191
                int kg = (idx & 3) * 8;          // 0..24
                int off = n * KS + kg;
                const size_t go = (size_t)n * DD + k0 + kg;
                *(uint4*)(sm + B_H + off) = *(const uint4*)(g_wh + go);
                *(uint4*)(sm + B_L + off) = *(const uint4*)(g_wl + go);
            }
        }
        __syncthreads();

        #pragma unroll
        for (int ks = 0; ks < 2; ++ks) {
            const int kk = ks * 16;
            uint32_t ah[2][4], al[2][4];
            #pragma unroll
            for (int mt = 0; mt < 2; ++mt) {
                uint32_t off = (uint32_t)((wm * 32 + mt * 16 + aRow) * KS + kk + aCol);
                ldsm4(ah[mt], sb + (A_H + off) * 2);
                ldsm4(al[mt], sb + (A_L + off) * 2);
            }
            #pragma unroll
            for (int np = 0; np < 3; ++np) {
                uint32_t boff = (uint32_t)((wn * 48 + np * 16 + bN) * KS + kk + bK);
                uint32_t bh[4], bl[4];
                ldsm4(bh, sb + (B_H + boff) * 2);
                ldsm4(bl, sb + (B_L + boff) * 2);
                #pragma unroll
                for (int mt = 0; mt < 2; ++mt)
                    #pragma unroll
                    for (int sub = 0; sub < 2; ++sub) {
                        float* cc = c[mt][np * 2 + sub];
                        mma16816(cc, ah[mt], bh[sub * 2], bh[sub * 2 + 1]);
                        mma16816(cc, ah[mt], bl[sub * 2], bl[sub * 2 + 1]);
                        mma16816(cc, al[mt], bh[sub * 2], bh[sub * 2 + 1]);
                    }
            }
        }
    }

    // ---- epilogue: scatter C to g_qkv (q|k|v by global column)
    const int t4 = lane >> 2;
    const int c2 = (lane & 3) * 2;
    #pragma unroll
    for (int mt = 0; mt < 2; ++mt)
        #pragma unroll
        for (int nt = 0; nt < 6; ++nt) {
            int col = wn * 48 + nt * 8 + c2;
            int sel = col >> 6;
            int hc  = col & 63;
            size_t base = (size_t)sel * HEADELEMS +
                          (size_t)(m0 + wm * 32 + mt * 16 + t4) * HH + hc;
            *(float2*)(g_qkv + base)          = make_float2(c[mt][nt][0], c[mt][nt][1]);
            *(float2*)(g_qkv + base + 8 * HH) = make_float2(c[mt][nt][2], c[mt][nt][3]);
        }
}

// ---------------------------------------------------------------------------
// Attention: unchanged (one CTA per batch, one thread per query row)
// ---------------------------------------------------------------------------
__global__ void __launch_bounds__(256, 1) attn_kernel(float* __restrict__ out)
{
    __shared__ __align__(16) float Ks[64][64];
    __shared__ __align__(16) float Vs[64][64];

    const int b = blockIdx.x;
    const int t = threadIdx.x;

    const float* qb = g_qkv + (size_t)b * TT * HH;
    const float* kb = g_qkv + HEADELEMS + (size_t)b * TT * HH;
    const float* vb = g_qkv + 2 * HEADELEMS + (size_t)b * TT * HH;

    float q[HH];
    {
        const float4* qr = (const float4*)(qb + (size_t)t * HH);
        #pragma unroll
        for (int j = 0; j < HH / 4; ++j) {
            float4 v = qr[j];
            q[4 * j + 0] = v.x * 0.125f;
            q[4 * j + 1] = v.y * 0.125f;
            q[4 * j + 2] = v.z * 0.125f;
            q[4 * j + 3] = v.w * 0.125f;
        }
    }

    float o[HH];
    #pragma unroll
    for (int j = 0; j < HH; ++j) o[j] = 0.f;
    float m = -1e30f;
    float l = 0.f;

    const int warp_tmax = t | 31;

    #pragma unroll 1
    for (int s0 = 0; s0 < TT; s0 += 64) {
        #pragma unroll
        for (int it = 0; it < 4; ++it) {
            int idx = t + it * 256;
            int r   = idx >> 4;
            int c   = (idx & 15) * 4;
            *(float4*)&Ks[r][c] = *(const float4*)(kb + (size_t)(s0 + r) * HH + c);
            *(float4*)&Vs[r][c] = *(const float4*)(vb + (size_t)(s0 + r) * HH + c);
        }
        __syncthreads();

        if (warp_tmax >= s0) {
            #pragma unroll 1
            for (int c0 = 0; c0 < 64; c0 += 8) {
                const int sbase = s0 + c0;
                if (t >= sbase) {
                    float sc[8];
                    #pragma unroll
                    for (int si = 0; si < 8; ++si) {
                        const float4* kr = (const float4*)&Ks[c0 + si][0];
                        float d0 = 0.f, d1 = 0.f, d2 = 0.f, d3 = 0.f;
                        #pragma unroll
                        for (int j = 0; j < 16; ++j) {
                            float4 kv = kr[j];
                            d0 = fmaf(q[4 * j + 0], kv.x, d0);
                            d1 = fmaf(q[4 * j + 1], kv.y, d1);
                            d2 = fmaf(q[4 * j + 2], kv.z, d2);
                            d3 = fmaf(q[4 * j + 3], kv.w, d3);
                        }
                        float d = (d0 + d1) + (d2 + d3);
                        sc[si] = (sbase + si <= t) ? d : -1e30f;
                    }
                    float cmax = sc[0];
                    #pragma unroll
                    for (int si = 1; si < 8; ++si) cmax = fmaxf(cmax, sc[si]);
                    float nm   = fmaxf(m, cmax);
                    float corr = __expf(m - nm);
                    m = nm;
                    l *= corr;
                    #pragma unroll
                    for (int j = 0; j < HH; ++j) o[j] *= corr;
                    #pragma unroll
                    for (int si = 0; si < 8; ++si) {
                        float p = __expf(sc[si] - nm);
                        l += p;
                        const float4* vr = (const float4*)&Vs[c0 + si][0];
                        #pragma unroll
                        for (int j = 0; j < 16; ++j) {
                            float4 vv = vr[j];
                            o[4 * j + 0] = fmaf(p, vv.x, o[4 * j + 0]);
                            o[4 * j + 1] = fmaf(p, vv.y, o[4 * j + 1]);
                            o[4 * j + 2] = fmaf(p, vv.z, o[4 * j + 2]);
                            o[4 * j + 3] = fmaf(p, vv.w, o[4 * j + 3]);
                        }
                    }
                }
            }
        }
        __syncthreads();
    }

    const float inv = 1.f / l;
    float4* orow = (float4*)(out + ((size_t)b * TT + t) * HH);
    #pragma unroll
    for (int j = 0; j < 16; ++j)
        orow[j] = make_float4(o[4 * j + 0] * inv, o[4 * j + 1] * inv,
                              o[4 * j + 2] * inv, o[4 * j + 3] * inv);
}

// ---------------------------------------------------------------------------
extern "C" void kernel_launch(void* const* d_in, const int* in_sizes, int n_in,
                              void* d_out, int out_size)
{
    const float* x  = (const float*)d_in[0];
    const float* Wq = (const float*)d_in[1];
    const float* Wk = (const float*)d_in[2];
    const float* Wv = (const float*)d_in[3];
    float* out = (float*)d_out;

    cudaFuncSetAttribute(proj_mma_kernel,
                         cudaFuncAttributeMaxDynamicSharedMemorySize, PROJ_SMEM);

    wsplit_kernel<<<(192 * 384 + 255) / 256, 256>>>(Wq, Wk, Wv);
    proj_mma_kernel<<<MTOT / 128, 512, PROJ_SMEM>>>(x);
    attn_kernel<<<BB, 256>>>(out);
}

// round 4
// speedup vs baseline: 2.1890x; 1.5121x over previous
#include <cuda_runtime.h>
#include <cuda_bf16.h>
#include <math.h>
#include <stdint.h>

#define BB   256
#define TT   256
#define DD   384
#define HH   64
#define MTOT (BB*TT)                       // 65536 rows
#define HEADELEMS ((size_t)MTOT*HH)

// scratch: q,k,v fp32 (50 MB) + split weights (transposed [n][k], bf16)
__device__ float g_qkv[3 * (size_t)MTOT * HH];
__device__ __nv_bfloat16 g_wh[192 * 384];
__device__ __nv_bfloat16 g_wl[192 * 384];

// ---------------------------------------------------------------------------
__device__ __forceinline__ uint32_t smem_u32(const void* p) {
    uint32_t a;
    asm("{ .reg .u64 t; cvta.to.shared.u64 t, %1; cvt.u32.u64 %0, t; }"
        : "=r"(a) : "l"(p));
    return a;
}

__device__ __forceinline__ void ldsm4(uint32_t r[4], uint32_t addr) {
    asm volatile("ldmatrix.sync.aligned.m8n8.x4.shared.b16 {%0,%1,%2,%3}, [%4];"
                 : "=r"(r[0]), "=r"(r[1]), "=r"(r[2]), "=r"(r[3]) : "r"(addr));
}

__device__ __forceinline__ void ldsm4t(uint32_t r[4], uint32_t addr) {
    asm volatile("ldmatrix.sync.aligned.m8n8.x4.trans.shared.b16 {%0,%1,%2,%3}, [%4];"
                 : "=r"(r[0]), "=r"(r[1]), "=r"(r[2]), "=r"(r[3]) : "r"(addr));
}

__device__ __forceinline__ void mma16816(float c[4], const uint32_t a[4],
                                         uint32_t b0, uint32_t b1) {
    asm volatile(
        "mma.sync.aligned.m16n8k16.row.col.f32.bf16.bf16.f32 "
        "{%0,%1,%2,%3}, {%4,%5,%6,%7}, {%8,%9}, {%0,%1,%2,%3};"
        : "+f"(c[0]), "+f"(c[1]), "+f"(c[2]), "+f"(c[3])
        : "r"(a[0]), "r"(a[1]), "r"(a[2]), "r"(a[3]), "r"(b0), "r"(b1));
}

// pack two f32 -> bf16x2 (lo in low half)
__device__ __forceinline__ uint32_t packbf(float lo, float hi) {
    uint32_t r;
    asm("cvt.rn.bf16x2.f32 %0, %1, %2;" : "=r"(r) : "f"(hi), "f"(lo));
    return r;
}

// ---------------------------------------------------------------------------
// Weight split prep
// ---------------------------------------------------------------------------
__global__ void wsplit_kernel(const float* __restrict__ Wq,
                              const float* __restrict__ Wk,
                              const float* __restrict__ Wv) {
    int i = blockIdx.x * 256 + threadIdx.x;
    if (i >= 192 * 384) return;
    int n = i / 384;
    int k = i % 384;
    const float* W = (n < 64) ? Wq : (n < 128) ? Wk : Wv;
    float v = W[(size_t)k * HH + (n & 63)];
    __nv_bfloat16 h = __float2bfloat16(v);
    float lo = v - __bfloat162float(h);
    g_wh[i] = h;
    g_wl[i] = __float2bfloat16(lo);
}

// ---------------------------------------------------------------------------
// mma.sync projection (unchanged from R3)
// ---------------------------------------------------------------------------
#define KC  32
#define KS  40
#define A_H 0
#define A_L 5120
#define B_H 10240
#define B_L 17920
#define PROJ_SMEM (25600 * 2)

__global__ void __launch_bounds__(512, 1) proj_mma_kernel(const float* __restrict__ x)
{
    extern __shared__ __nv_bfloat16 sm[];
    const uint32_t sb = smem_u32(sm);
    const int tid  = threadIdx.x;
    const int lane = tid & 31;
    const int wid  = tid >> 5;
    const int wm   = wid & 3;
    const int wn   = wid >> 2;
    const int m0   = blockIdx.x * 128;

    const int aRow = (lane & 7) + ((lane >> 3) & 1) * 8;
    const int aCol = ((lane >> 4) & 1) * 8;
    const int bN   = (lane & 7) + ((lane >> 4) & 1) * 8;
    const int bK   = ((lane >> 3) & 1) * 8;

    float c[2][6][4];
    #pragma unroll
    for (int mt = 0; mt < 2; ++mt)
        #pragma unroll
        for (int nt = 0; nt < 6; ++nt)
            #pragma unroll
            for (int j = 0; j < 4; ++j) c[mt][nt][j] = 0.f;

    #pragma unroll 1
    for (int ch = 0; ch < 12; ++ch) {
        const int k0 = ch * KC;
        if (ch) __syncthreads();

        #pragma unroll
        for (int it = 0; it < 2; ++it) {
            int idx = tid + it * 512;
            int r   = idx >> 3;
            int c4  = (idx & 7) * 4;
            float4 v = *(const float4*)(x + (size_t)(m0 + r) * DD + k0 + c4);
            __nv_bfloat16 h0 = __float2bfloat16(v.x);
            __nv_bfloat16 h1 = __float2bfloat16(v.y);
            __nv_bfloat16 h2 = __float2bfloat16(v.z);
            __nv_bfloat16 h3 = __float2bfloat16(v.w);
            __nv_bfloat16 l0 = __float2bfloat16(v.x - __bfloat162float(h0));
            __nv_bfloat16 l1 = __float2bfloat16(v.y - __bfloat162float(h1));
            __nv_bfloat16 l2 = __float2bfloat16(v.z - __bfloat162float(h2));
            __nv_bfloat16 l3 = __float2bfloat16(v.w - __bfloat162float(h3));
            uint32_t hp0 = ((uint32_t)__bfloat16_as_ushort(h1) << 16) | __bfloat16_as_ushort(h0);
            uint32_t hp1 = ((uint32_t)__bfloat16_as_ushort(h3) << 16) | __bfloat16_as_ushort(h2);
            uint32_t lp0 = ((uint32_t)__bfloat16_as_ushort(l1) << 16) | __bfloat16_as_ushort(l0);
            uint32_t lp1 = ((uint32_t)__bfloat16_as_ushort(l3) << 16) | __bfloat16_as_ushort(l2);
            int off = r * KS + c4;
            *(uint2*)(sm + A_H + off) = make_uint2(hp0, hp1);
            *(uint2*)(sm + A_L + off) = make_uint2(lp0, lp1);
        }

        #pragma unroll
        for (int it = 0; it < 2; ++it) {
            int idx = tid + it * 512;
            if (idx < 768) {
                int n  = idx >> 2;
                int kg = (idx & 3) * 8;
                int off = n * KS + kg;
                const size_t go = (size_t)n * DD + k0 + kg;
                *(uint4*)(sm + B_H + off) = *(const uint4*)(g_wh + go);
                *(uint4*)(sm + B_L + off) = *(const uint4*)(g_wl + go);
            }
        }
        __syncthreads();

        #pragma unroll
        for (int ks = 0; ks < 2; ++ks) {
            const int kk = ks * 16;
            uint32_t ah[2][4], al[2][4];
            #pragma unroll
            for (int mt = 0; mt < 2; ++mt) {
                uint32_t off = (uint32_t)((wm * 32 + mt * 16 + aRow) * KS + kk + aCol);
                ldsm4(ah[mt], sb + (A_H + off) * 2);
                ldsm4(al[mt], sb + (A_L + off) * 2);
            }
            #pragma unroll
            for (int np = 0; np < 3; ++np) {
                uint32_t boff = (uint32_t)((wn * 48 + np * 16 + bN) * KS + kk + bK);
                uint32_t bh[4], bl[4];
                ldsm4(bh, sb + (B_H + boff) * 2);
                ldsm4(bl, sb + (B_L + boff) * 2);
                #pragma unroll
                for (int mt = 0; mt < 2; ++mt)
                    #pragma unroll
                    for (int sub = 0; sub < 2; ++sub) {
                        float* cc = c[mt][np * 2 + sub];
                        mma16816(cc, ah[mt], bh[sub * 2], bh[sub * 2 + 1]);
                        mma16816(cc, ah[mt], bl[sub * 2], bl[sub * 2 + 1]);
                        mma16816(cc, al[mt], bh[sub * 2], bh[sub * 2 + 1]);
                    }
            }
        }
    }

    const int t4 = lane >> 2;
    const int c2 = (lane & 3) * 2;
    #pragma unroll
    for (int mt = 0; mt < 2; ++mt)
        #pragma unroll
        for (int nt = 0; nt < 6; ++nt) {
            int col = wn * 48 + nt * 8 + c2;
            int sel = col >> 6;
            int hc  = col & 63;
            size_t base = (size_t)sel * HEADELEMS +
                          (size_t)(m0 + wm * 32 + mt * 16 + t4) * HH + hc;
            *(float2*)(g_qkv + base)          = make_float2(c[mt][nt][0], c[mt][nt][1]);
            *(float2*)(g_qkv + base + 8 * HH) = make_float2(c[mt][nt][2], c[mt][nt][3]);
        }
}

// ---------------------------------------------------------------------------
// Tensor-core flash attention. One CTA per batch, 8 warps.
// Warp w owns m-tiles at rows 16w and 240-16w (balanced causal work: 5 mt-tiles).
// smem: q,k,v split hi/lo bf16, row stride 72 halves (conflict-free ldmatrix).
// ---------------------------------------------------------------------------
#define AST 72
#define Q_HI 0
#define Q_LO (256*AST)
#define K_HI (2*256*AST)
#define K_LO (3*256*AST)
#define V_HI (4*256*AST)
#define V_LO (5*256*AST)
#define ATTN_SMEM (6*256*AST*2)    // 221184 bytes

__global__ void __launch_bounds__(256, 1) attn_mma_kernel(float* __restrict__ out)
{
    extern __shared__ __nv_bfloat16 asmem[];
    const uint32_t sb = smem_u32(asmem);
    const int b    = blockIdx.x;
    const int tid  = threadIdx.x;
    const int lane = tid & 31;
    const int w    = tid >> 5;
    const int t4   = lane >> 2;
    const int tg   = lane & 3;

    // ---- load q,k,v (fp32) -> split bf16 smem
    #pragma unroll
    for (int sel = 0; sel < 3; ++sel) {
        const float* src = g_qkv + (size_t)sel * HEADELEMS + (size_t)b * TT * HH;
        const float scale = (sel == 0) ? 0.125f : 1.0f;
        const int hi_off = sel * 2 * 256 * AST;
        const int lo_off = hi_off + 256 * AST;
        #pragma unroll
        for (int it = 0; it < 16; ++it) {
            int idx = tid + it * 256;           // 0..4095 float4s
            int r   = idx >> 4;
            int c4  = (idx & 15) * 4;
            float4 v = *(const float4*)(src + (size_t)r * HH + c4);
            v.x *= scale; v.y *= scale; v.z *= scale; v.w *= scale;
            __nv_bfloat16 h0 = __float2bfloat16(v.x);
            __nv_bfloat16 h1 = __float2bfloat16(v.y);
            __nv_bfloat16 h2 = __float2bfloat16(v.z);
            __nv_bfloat16 h3 = __float2bfloat16(v.w);
            __nv_bfloat16 l0 = __float2bfloat16(v.x - __bfloat162float(h0));
            __nv_bfloat16 l1 = __float2bfloat16(v.y - __bfloat162float(h1));
            __nv_bfloat16 l2 = __float2bfloat16(v.z - __bfloat162float(h2));
            __nv_bfloat16 l3 = __float2bfloat16(v.w - __bfloat162float(h3));
            uint32_t hp0 = ((uint32_t)__bfloat16_as_ushort(h1) << 16) | __bfloat16_as_ushort(h0);
            uint32_t hp1 = ((uint32_t)__bfloat16_as_ushort(h3) << 16) | __bfloat16_as_ushort(h2);
            uint32_t lp0 = ((uint32_t)__bfloat16_as_ushort(l1) << 16) | __bfloat16_as_ushort(l0);
            uint32_t lp1 = ((uint32_t)__bfloat16_as_ushort(l3) << 16) | __bfloat16_as_ushort(l2);
            int off = r * AST + c4;
            *(uint2*)(asmem + hi_off + off) = make_uint2(hp0, hp1);
            *(uint2*)(asmem + lo_off + off) = make_uint2(lp0, lp1);
        }
    }
    __syncthreads();

    const int Rb[2] = { 16 * w, 240 - 16 * w };

    float o[2][8][4];
    float mrow[2][2], lrow[2][2];
    #pragma unroll
    for (int mt = 0; mt < 2; ++mt) {
        mrow[mt][0] = mrow[mt][1] = -1e30f;
        lrow[mt][0] = lrow[mt][1] = 0.f;
        #pragma unroll
        for (int nt = 0; nt < 8; ++nt)
            #pragma unroll
            for (int j = 0; j < 4; ++j) o[mt][nt][j] = 0.f;
    }

    // ldmatrix lane address components
    const int qRow = lane & 15;
    const int qCol = ((lane >> 4) & 1) * 8;
    const int kRow = (lane & 7) + ((lane >> 4) & 1) * 8;   // n within 16
    const int kCol = ((lane >> 3) & 1) * 8;                // k within 16
    const int vRow = lane & 15;                            // k within 16
    const int vCol = ((lane >> 4) & 1) * 8;                // n within 16

    #pragma unroll 1
    for (int s0 = 0; s0 < TT; s0 += 64) {
        #pragma unroll
        for (int mt = 0; mt < 2; ++mt) {
            const int base = Rb[mt];
            if (s0 > base + 15) continue;

            // ---- S = Q K^T (split bf16, 3 products)
            float sc[8][4];
            #pragma unroll
            for (int nt = 0; nt < 8; ++nt)
                #pragma unroll
                for (int j = 0; j < 4; ++j) sc[nt][j] = 0.f;

            #pragma unroll
            for (int kc = 0; kc < 4; ++kc) {
                uint32_t qh[4], ql[4];
                uint32_t qoff = (uint32_t)((base + qRow) * AST + kc * 16 + qCol);
                ldsm4(qh, sb + (Q_HI + qoff) * 2);
                ldsm4(ql, sb + (Q_LO + qoff) * 2);
                #pragma unroll
                for (int np = 0; np < 4; ++np) {
                    uint32_t koff = (uint32_t)((s0 + np * 16 + kRow) * AST + kc * 16 + kCol);
                    uint32_t kh[4], kl[4];
                    ldsm4(kh, sb + (K_HI + koff) * 2);
                    ldsm4(kl, sb + (K_LO + koff) * 2);
                    mma16816(sc[2 * np],     qh, kh[0], kh[1]);
                    mma16816(sc[2 * np],     qh, kl[0], kl[1]);
                    mma16816(sc[2 * np],     ql, kh[0], kh[1]);
                    mma16816(sc[2 * np + 1], qh, kh[2], kh[3]);
                    mma16816(sc[2 * np + 1], qh, kl[2], kl[3]);
                    mma16816(sc[2 * np + 1], ql, kh[2], kh[3]);
                }
            }

            // ---- causal mask + online softmax
            const int r0 = base + t4;
            const int r1 = r0 + 8;
            #pragma unroll
            for (int nt = 0; nt < 8; ++nt) {
                int col = s0 + 8 * nt + 2 * tg;
                if (col     > r0) sc[nt][0] = -1e30f;
                if (col + 1 > r0) sc[nt][1] = -1e30f;
                if (col     > r1) sc[nt][2] = -1e30f;
                if (col + 1 > r1) sc[nt][3] = -1e30f;
            }
            float mx0 = sc[0][0], mx1 = sc[0][2];
            #pragma unroll
            for (int nt = 0; nt < 8; ++nt) {
                mx0 = fmaxf(mx0, fmaxf(sc[nt][0], sc[nt][1]));
                mx1 = fmaxf(mx1, fmaxf(sc[nt][2], sc[nt][3]));
            }
            mx0 = fmaxf(mx0, __shfl_xor_sync(0xffffffffu, mx0, 1));
            mx0 = fmaxf(mx0, __shfl_xor_sync(0xffffffffu, mx0, 2));
            mx1 = fmaxf(mx1, __shfl_xor_sync(0xffffffffu, mx1, 1));
            mx1 = fmaxf(mx1, __shfl_xor_sync(0xffffffffu, mx1, 2));

            float nm0 = fmaxf(mrow[mt][0], mx0);
            float nm1 = fmaxf(mrow[mt][1], mx1);
            float corr0 = __expf(mrow[mt][0] - nm0);
            float corr1 = __expf(mrow[mt][1] - nm1);
            mrow[mt][0] = nm0;
            mrow[mt][1] = nm1;

            float sum0 = 0.f, sum1 = 0.f;
            #pragma unroll
            for (int nt = 0; nt < 8; ++nt) {
                sc[nt][0] = __expf(sc[nt][0] - nm0);
                sc[nt][1] = __expf(sc[nt][1] - nm0);
                sc[nt][2] = __expf(sc[nt][2] - nm1);
                sc[nt][3] = __expf(sc[nt][3] - nm1);
                sum0 += sc[nt][0] + sc[nt][1];
                sum1 += sc[nt][2] + sc[nt][3];
            }
            sum0 += __shfl_xor_sync(0xffffffffu, sum0, 1);
            sum0 += __shfl_xor_sync(0xffffffffu, sum0, 2);
            sum1 += __shfl_xor_sync(0xffffffffu, sum1, 1);
            sum1 += __shfl_xor_sync(0xffffffffu, sum1, 2);
            lrow[mt][0] = lrow[mt][0] * corr0 + sum0;
            lrow[mt][1] = lrow[mt][1] * corr1 + sum1;

            #pragma unroll
            for (int nt = 0; nt < 8; ++nt) {
                o[mt][nt][0] *= corr0;
                o[mt][nt][1] *= corr0;
                o[mt][nt][2] *= corr1;
                o[mt][nt][3] *= corr1;
            }

            // ---- O += P V (split bf16, 3 products)
            #pragma unroll
            for (int kv = 0; kv < 4; ++kv) {
                // build P hi/lo A-fragments from sc n-tiles 2kv, 2kv+1
                uint32_t ph[4], pl[4];
                #pragma unroll
                for (int half = 0; half < 2; ++half) {
                    const float* f = sc[2 * kv + half];
                    __nv_bfloat16 h0 = __float2bfloat16(f[0]);
                    __nv_bfloat16 h1 = __float2bfloat16(f[1]);
                    __nv_bfloat16 h2 = __float2bfloat16(f[2]);
                    __nv_bfloat16 h3 = __float2bfloat16(f[3]);
                    ph[2 * half]     = ((uint32_t)__bfloat16_as_ushort(h1) << 16) |
                                       __bfloat16_as_ushort(h0);
                    ph[2 * half + 1] = ((uint32_t)__bfloat16_as_ushort(h3) << 16) |
                                       __bfloat16_as_ushort(h2);
                    pl[2 * half]     = packbf(f[0] - __bfloat162float(h0),
                                              f[1] - __bfloat162float(h1));
                    pl[2 * half + 1] = packbf(f[2] - __bfloat162float(h2),
                                              f[3] - __bfloat162float(h3));
                }
                #pragma unroll
                for (int np = 0; np < 4; ++np) {
                    uint32_t voff = (uint32_t)((s0 + kv * 16 + vRow) * AST + np * 16 + vCol);
                    uint32_t vh[4], vl[4];
                    ldsm4t(vh, sb + (V_HI + voff) * 2);
                    ldsm4t(vl, sb + (V_LO + voff) * 2);
                    mma16816(o[mt][2 * np],     ph, vh[0], vh[1]);
                    mma16816(o[mt][2 * np],     ph, vl[0], vl[1]);
                    mma16816(o[mt][2 * np],     pl, vh[0], vh[1]);
                    mma16816(o[mt][2 * np + 1], ph, vh[2], vh[3]);
                    mma16816(o[mt][2 * np + 1], ph, vl[2], vl[3]);
                    mma16816(o[mt][2 * np + 1], pl, vh[2], vh[3]);
                }
            }
        }
    }

    // ---- write out
    #pragma unroll
    for (int mt = 0; mt < 2; ++mt) {
        const int r0 = Rb[mt] + t4;
        const float inv0 = 1.f / lrow[mt][0];
        const float inv1 = 1.f / lrow[mt][1];
        #pragma unroll
        for (int nt = 0; nt < 8; ++nt) {
            int col = 8 * nt + 2 * tg;
            size_t o0 = ((size_t)b * TT + r0) * HH + col;
            *(float2*)(out + o0)           = make_float2(o[mt][nt][0] * inv0,
                                                         o[mt][nt][1] * inv0);
            *(float2*)(out + o0 + 8 * HH)  = make_float2(o[mt][nt][2] * inv1,
                                                         o[mt][nt][3] * inv1);
        }
    }
}

// ---------------------------------------------------------------------------
extern "C" void kernel_launch(void* const* d_in, const int* in_sizes, int n_in,
                              void* d_out, int out_size)
{
    const float* x  = (const float*)d_in[0];
    const float* Wq = (const float*)d_in[1];
    const float* Wk = (const float*)d_in[2];
    const float* Wv = (const float*)d_in[3];
    float* out = (float*)d_out;

    cudaFuncSetAttribute(proj_mma_kernel,
                         cudaFuncAttributeMaxDynamicSharedMemorySize, PROJ_SMEM);
    cudaFuncSetAttribute(attn_mma_kernel,
                         cudaFuncAttributeMaxDynamicSharedMemorySize, ATTN_SMEM);

    wsplit_kernel<<<(192 * 384 + 255) / 256, 256>>>(Wq, Wk, Wv);
    proj_mma_kernel<<<MTOT / 128, 512, PROJ_SMEM>>>(x);
    attn_mma_kernel<<<BB, 256, ATTN_SMEM>>>(out);
}

// round 6
// speedup vs baseline: 2.4935x; 1.1391x over previous
#include <cuda_runtime.h>
#include <cuda_bf16.h>
#include <math.h>
#include <stdint.h>

#define BB   256
#define TT   256
#define DD   384
#define HH   64
#define MTOT (BB*TT)                       // 65536 rows
#define HEADELEMS ((size_t)MTOT*HH)

// scratch: q,k,v split bf16 hi/lo + split weights (transposed [n][k], bf16)
__device__ __nv_bfloat16 g_h[3 * (size_t)MTOT * HH];
__device__ __nv_bfloat16 g_l[3 * (size_t)MTOT * HH];
__device__ __nv_bfloat16 g_wh[192 * 384];
__device__ __nv_bfloat16 g_wl[192 * 384];

// ---------------------------------------------------------------------------
__device__ __forceinline__ uint32_t smem_u32(const void* p) {
    uint32_t a;
    asm("{ .reg .u64 t; cvta.to.shared.u64 t, %1; cvt.u32.u64 %0, t; }"
        : "=r"(a) : "l"(p));
    return a;
}

__device__ __forceinline__ void ldsm4(uint32_t r[4], uint32_t addr) {
    asm volatile("ldmatrix.sync.aligned.m8n8.x4.shared.b16 {%0,%1,%2,%3}, [%4];"
                 : "=r"(r[0]), "=r"(r[1]), "=r"(r[2]), "=r"(r[3]) : "r"(addr));
}

__device__ __forceinline__ void ldsm4t(uint32_t r[4], uint32_t addr) {
    asm volatile("ldmatrix.sync.aligned.m8n8.x4.trans.shared.b16 {%0,%1,%2,%3}, [%4];"
                 : "=r"(r[0]), "=r"(r[1]), "=r"(r[2]), "=r"(r[3]) : "r"(addr));
}

__device__ __forceinline__ void mma16816(float c[4], const uint32_t a[4],
                                         uint32_t b0, uint32_t b1) {
    asm volatile(
        "mma.sync.aligned.m16n8k16.row.col.f32.bf16.bf16.f32 "
        "{%0,%1,%2,%3}, {%4,%5,%6,%7}, {%8,%9}, {%0,%1,%2,%3};"
        : "+f"(c[0]), "+f"(c[1]), "+f"(c[2]), "+f"(c[3])
        : "r"(a[0]), "r"(a[1]), "r"(a[2]), "r"(a[3]), "r"(b0), "r"(b1));
}

// pack two f32 -> bf16x2 (first arg in low half)
__device__ __forceinline__ uint32_t packbf(float lo, float hi) {
    uint32_t r;
    asm("cvt.rn.bf16x2.f32 %0, %1, %2;" : "=r"(r) : "f"(hi), "f"(lo));
    return r;
}

__device__ __forceinline__ void cpasync16(uint32_t dst, const void* src) {
    asm volatile("cp.async.cg.shared.global [%0], [%1], 16;"
                 :: "r"(dst), "l"(src));
}

// ---------------------------------------------------------------------------
// Weight split prep
// ---------------------------------------------------------------------------
__global__ void wsplit_kernel(const float* __restrict__ Wq,
                              const float* __restrict__ Wk,
                              const float* __restrict__ Wv) {
    int i = blockIdx.x * 256 + threadIdx.x;
    if (i >= 192 * 384) return;
    int n = i / 384;
    int k = i % 384;
    const float* W = (n < 64) ? Wq : (n < 128) ? Wk : Wv;
    float v = W[(size_t)k * HH + (n & 63)];
    __nv_bfloat16 h = __float2bfloat16(v);
    float lo = v - __bfloat162float(h);
    g_wh[i] = h;
    g_wl[i] = __float2bfloat16(lo);
}

// ---------------------------------------------------------------------------
// Pipelined mma.sync projection.
// A: fp32 x -> register LDG -> convert -> STS, stride 40 halves, double buf.
// B: cp.async bf16 from g_wh/g_wl, stride 56 halves, double buf.
// One __syncthreads per chunk; B(c+1)/A(c+1) loads overlap MMA(c).
// ---------------------------------------------------------------------------
#define KC   32
#define KS   40
#define KSB  56
#define ABUF 5120    // halves: 128*40
#define BBUF 10752   // halves: 192*56
#define B_BASE 20480 // halves: 2 A-bufs * (2*5120)
#define PROJ_SMEM ((20480 + 43008) * 2)   // 126976 bytes

__global__ void __launch_bounds__(512, 1) proj_mma_kernel(const float* __restrict__ x)
{
    extern __shared__ __nv_bfloat16 sm[];
    const uint32_t sb = smem_u32(sm);
    const int tid  = threadIdx.x;
    const int lane = tid & 31;
    const int wid  = tid >> 5;
    const int wm   = wid & 3;
    const int wn   = wid >> 2;
    const int m0   = blockIdx.x * 128;

    const int aRow = (lane & 7) + ((lane >> 3) & 1) * 8;
    const int aCol = ((lane >> 4) & 1) * 8;
    const int bN   = (lane & 7) + ((lane >> 4) & 1) * 8;
    const int bK   = ((lane >> 3) & 1) * 8;

    float c[2][6][4];
    #pragma unroll
    for (int mt = 0; mt < 2; ++mt)
        #pragma unroll
        for (int nt = 0; nt < 6; ++nt)
            #pragma unroll
            for (int j = 0; j < 4; ++j) c[mt][nt][j] = 0.f;

    float4 aCur[2], aNxt[2];

    // ---- prologue: B(0) cp.async -> buf0, A(0) -> regs
    {
        const int k0 = 0;
        #pragma unroll
        for (int it = 0; it < 3; ++it) {
            int idx = tid + it * 512;              // 0..1535
            int sub = (idx < 768) ? idx : idx - 768;
            int n   = sub >> 2;
            int kg  = (sub & 3) * 8;
            const __nv_bfloat16* src =
                ((idx < 768) ? g_wh : g_wl) + (size_t)n * DD + k0 + kg;
            uint32_t dst = sb + (uint32_t)(B_BASE + ((idx < 768) ? 0 : BBUF) +
                                           n * KSB + kg) * 2;
            cpasync16(dst, src);
        }
        asm volatile("cp.async.commit_group;" ::: "memory");
        #pragma unroll
        for (int it = 0; it < 2; ++it) {
            int idx = tid + it * 512;
            int r = idx >> 3, c4 = (idx & 7) * 4;
            aCur[it] = *(const float4*)(x + (size_t)(m0 + r) * DD + k0 + c4);
        }
    }

    int p = 0;
    #pragma unroll 1
    for (int ch = 0; ch < 12; ++ch) {
        // ---- STS A(ch) into bufA[p] (convert fp32 -> hi/lo bf16)
        #pragma unroll
        for (int it = 0; it < 2; ++it) {
            int idx = tid + it * 512;
            int r = idx >> 3, c4 = (idx & 7) * 4;
            float4 v = aCur[it];
            __nv_bfloat16 h0 = __float2bfloat16(v.x);
            __nv_bfloat16 h1 = __float2bfloat16(v.y);
            __nv_bfloat16 h2 = __float2bfloat16(v.z);
            __nv_bfloat16 h3 = __float2bfloat16(v.w);
            uint32_t hp0 = ((uint32_t)__bfloat16_as_ushort(h1) << 16) | __bfloat16_as_ushort(h0);
            uint32_t hp1 = ((uint32_t)__bfloat16_as_ushort(h3) << 16) | __bfloat16_as_ushort(h2);
            uint32_t lp0 = packbf(v.x - __bfloat162float(h0), v.y - __bfloat162float(h1));
            uint32_t lp1 = packbf(v.z - __bfloat162float(h2), v.w - __bfloat162float(h3));
            int off = p * 10240 + r * KS + c4;
            *(uint2*)(sm + off)        = make_uint2(hp0, hp1);
            *(uint2*)(sm + off + ABUF) = make_uint2(lp0, lp1);
        }

        // ---- drain B(ch), barrier
        asm volatile("cp.async.wait_group 0;" ::: "memory");
        __syncthreads();

        // ---- issue B(ch+1) + LDG A(ch+1); overlaps the MMA phase below
        if (ch < 11) {
            const int k1 = (ch + 1) * KC;
            #pragma unroll
            for (int it = 0; it < 3; ++it) {
                int idx = tid + it * 512;
                int sub = (idx < 768) ? idx : idx - 768;
                int n   = sub >> 2;
                int kg  = (sub & 3) * 8;
                const __nv_bfloat16* src =
                    ((idx < 768) ? g_wh : g_wl) + (size_t)n * DD + k1 + kg;
                uint32_t dst = sb + (uint32_t)(B_BASE + (p ^ 1) * 21504 +
                                               ((idx < 768) ? 0 : BBUF) +
                                               n * KSB + kg) * 2;
                cpasync16(dst, src);
            }
            asm volatile("cp.async.commit_group;" ::: "memory");
            #pragma unroll
            for (int it = 0; it < 2; ++it) {
                int idx = tid + it * 512;
                int r = idx >> 3, c4 = (idx & 7) * 4;
                aNxt[it] = *(const float4*)(x + (size_t)(m0 + r) * DD + k1 + c4);
            }
        }

        // ---- MMA over buffers p
        const uint32_t aBase = (uint32_t)(p * 10240);
        const uint32_t bBase = (uint32_t)(B_BASE + p * 21504);
        #pragma unroll
        for (int ks = 0; ks < 2; ++ks) {
            const int kk = ks * 16;
            uint32_t ah[2][4], al[2][4];
            #pragma unroll
            for (int mt = 0; mt < 2; ++mt) {
                uint32_t off = (uint32_t)((wm * 32 + mt * 16 + aRow) * KS + kk + aCol);
                ldsm4(ah[mt], sb + (aBase + off) * 2);
                ldsm4(al[mt], sb + (aBase + ABUF + off) * 2);
            }
            #pragma unroll
            for (int np = 0; np < 3; ++np) {
                uint32_t boff = (uint32_t)((wn * 48 + np * 16 + bN) * KSB + kk + bK);
                uint32_t bh[4], bl[4];
                ldsm4(bh, sb + (bBase + boff) * 2);
                ldsm4(bl, sb + (bBase + BBUF + boff) * 2);
                #pragma unroll
                for (int mt = 0; mt < 2; ++mt)
                    #pragma unroll
                    for (int sub = 0; sub < 2; ++sub) {
                        float* cc = c[mt][sub + np * 2];
                        mma16816(cc, ah[mt], bh[sub * 2], bh[sub * 2 + 1]);
                        mma16816(cc, ah[mt], bl[sub * 2], bl[sub * 2 + 1]);
                        mma16816(cc, al[mt], bh[sub * 2], bh[sub * 2 + 1]);
                    }
            }
        }

        aCur[0] = aNxt[0];
        aCur[1] = aNxt[1];
        p ^= 1;
    }

    // ---- epilogue: fp32 acc -> hi/lo bf16 to g_h/g_l (q pre-scaled by 0.125)
    const int t4 = lane >> 2;
    const int c2 = (lane & 3) * 2;
    #pragma unroll
    for (int mt = 0; mt < 2; ++mt)
        #pragma unroll
        for (int nt = 0; nt < 6; ++nt) {
            int col = wn * 48 + nt * 8 + c2;
            int sel = col >> 6;
            int hc  = col & 63;
            float s = (sel == 0) ? 0.125f : 1.0f;
            float v0 = c[mt][nt][0] * s, v1 = c[mt][nt][1] * s;
            float v2 = c[mt][nt][2] * s, v3 = c[mt][nt][3] * s;
            __nv_bfloat16 h0 = __float2bfloat16(v0);
            __nv_bfloat16 h1 = __float2bfloat16(v1);
            __nv_bfloat16 h2 = __float2bfloat16(v2);
            __nv_bfloat16 h3 = __float2bfloat16(v3);
            size_t base = (size_t)sel * HEADELEMS +
                          (size_t)(m0 + wm * 32 + mt * 16 + t4) * HH + hc;
            *(uint32_t*)(g_h + base) =
                ((uint32_t)__bfloat16_as_ushort(h1) << 16) | __bfloat16_as_ushort(h0);
            *(uint32_t*)(g_h + base + 8 * HH) =
                ((uint32_t)__bfloat16_as_ushort(h3) << 16) | __bfloat16_as_ushort(h2);
            *(uint32_t*)(g_l + base) =
                packbf(v0 - __bfloat162float(h0), v1 - __bfloat162float(h1));
            *(uint32_t*)(g_l + base + 8 * HH) =
                packbf(v2 - __bfloat162float(h2), v3 - __bfloat162float(h3));
        }
}

// ---------------------------------------------------------------------------
// Tensor-core flash attention. One CTA per batch, 8 warps.
// Load phase = pure cp.async of pre-split bf16 q/k/v (q pre-scaled).
// ---------------------------------------------------------------------------
#define AST 72
#define Q_HI 0
#define Q_LO (256*AST)
#define K_HI (2*256*AST)
#define K_LO (3*256*AST)
#define V_HI (4*256*AST)
#define V_LO (5*256*AST)
#define ATTN_SMEM (6*256*AST*2)    // 221184 bytes

__global__ void __launch_bounds__(256, 1) attn_mma_kernel(float* __restrict__ out)
{
    extern __shared__ __nv_bfloat16 asmem[];
    const uint32_t sb = smem_u32(asmem);
    const int b    = blockIdx.x;
    const int tid  = threadIdx.x;
    const int lane = tid & 31;
    const int w    = tid >> 5;
    const int t4   = lane >> 2;
    const int tg   = lane & 3;

    // ---- cp.async load: 6 arrays (q/k/v hi,lo) of [256][64] bf16 -> stride-72 smem
    #pragma unroll
    for (int it = 0; it < 48; ++it) {
        int idx = tid + it * 256;              // 0..12287
        int arr = idx >> 11;                   // 0..5: q_hi,q_lo,k_hi,k_lo,v_hi,v_lo
        int rem = idx & 2047;
        int r   = rem >> 3;
        int kg  = (rem & 7) * 8;
        const __nv_bfloat16* src = ((arr & 1) ? g_l : g_h) +
            (size_t)(arr >> 1) * HEADELEMS + ((size_t)b * TT + r) * HH + kg;
        uint32_t dst = sb + (uint32_t)(arr * 256 * AST + r * AST + kg) * 2;
        cpasync16(dst, src);
    }
    asm volatile("cp.async.commit_group;\n\tcp.async.wait_group 0;" ::: "memory");
    __syncthreads();

    const int Rb[2] = { 16 * w, 240 - 16 * w };

    float o[2][8][4];
    float mrow[2][2], lrow[2][2];
    #pragma unroll
    for (int mt = 0; mt < 2; ++mt) {
        mrow[mt][0] = mrow[mt][1] = -1e30f;
        lrow[mt][0] = lrow[mt][1] = 0.f;
        #pragma unroll
        for (int nt = 0; nt < 8; ++nt)
            #pragma unroll
            for (int j = 0; j < 4; ++j) o[mt][nt][j] = 0.f;
    }

    const int qRow = lane & 15;
    const int qCol = ((lane >> 4) & 1) * 8;
    const int kRow = (lane & 7) + ((lane >> 4) & 1) * 8;
    const int kCol = ((lane >> 3) & 1) * 8;
    const int vRow = lane & 15;
    const int vCol = ((lane >> 4) & 1) * 8;

    #pragma unroll 1
    for (int s0 = 0; s0 < TT; s0 += 64) {
        #pragma unroll
        for (int mt = 0; mt < 2; ++mt) {
            const int base = Rb[mt];
            if (s0 > base + 15) continue;

            // ---- S = Q K^T (split bf16, 3 products)
            float sc[8][4];
            #pragma unroll
            for (int nt = 0; nt < 8; ++nt)
                #pragma unroll
                for (int j = 0; j < 4; ++j) sc[nt][j] = 0.f;

            #pragma unroll
            for (int kc = 0; kc < 4; ++kc) {
                uint32_t qh[4], ql[4];
                uint32_t qoff = (uint32_t)((base + qRow) * AST + kc * 16 + qCol);
                ldsm4(qh, sb + (Q_HI + qoff) * 2);
                ldsm4(ql, sb + (Q_LO + qoff) * 2);
                #pragma unroll
                for (int np = 0; np < 4; ++np) {
                    uint32_t koff = (uint32_t)((s0 + np * 16 + kRow) * AST + kc * 16 + kCol);
                    uint32_t kh[4], kl[4];
                    ldsm4(kh, sb + (K_HI + koff) * 2);
                    ldsm4(kl, sb + (K_LO + koff) * 2);
                    mma16816(sc[2 * np],     qh, kh[0], kh[1]);
                    mma16816(sc[2 * np],     qh, kl[0], kl[1]);
                    mma16816(sc[2 * np],     ql, kh[0], kh[1]);
                    mma16816(sc[2 * np + 1], qh, kh[2], kh[3]);
                    mma16816(sc[2 * np + 1], qh, kl[2], kl[3]);
                    mma16816(sc[2 * np + 1], ql, kh[2], kh[3]);
                }
            }

            // ---- causal mask + online softmax
            const int r0 = base + t4;
            const int r1 = r0 + 8;
            #pragma unroll
            for (int nt = 0; nt < 8; ++nt) {
                int col = s0 + 8 * nt + 2 * tg;
                if (col     > r0) sc[nt][0] = -1e30f;
                if (col + 1 > r0) sc[nt][1] = -1e30f;
                if (col     > r1) sc[nt][2] = -1e30f;
                if (col + 1 > r1) sc[nt][3] = -1e30f;
            }
            float mx0 = sc[0][0], mx1 = sc[0][2];
            #pragma unroll
            for (int nt = 0; nt < 8; ++nt) {
                mx0 = fmaxf(mx0, fmaxf(sc[nt][0], sc[nt][1]));
                mx1 = fmaxf(mx1, fmaxf(sc[nt][2], sc[nt][3]));
            }
            mx0 = fmaxf(mx0, __shfl_xor_sync(0xffffffffu, mx0, 1));
            mx0 = fmaxf(mx0, __shfl_xor_sync(0xffffffffu, mx0, 2));
            mx1 = fmaxf(mx1, __shfl_xor_sync(0xffffffffu, mx1, 1));
            mx1 = fmaxf(mx1, __shfl_xor_sync(0xffffffffu, mx1, 2));

            float nm0 = fmaxf(mrow[mt][0], mx0);
            float nm1 = fmaxf(mrow[mt][1], mx1);
            float corr0 = __expf(mrow[mt][0] - nm0);
            float corr1 = __expf(mrow[mt][1] - nm1);
            mrow[mt][0] = nm0;
            mrow[mt][1] = nm1;

            float sum0 = 0.f, sum1 = 0.f;
            #pragma unroll
            for (int nt = 0; nt < 8; ++nt) {
                sc[nt][0] = __expf(sc[nt][0] - nm0);
                sc[nt][1] = __expf(sc[nt][1] - nm0);
                sc[nt][2] = __expf(sc[nt][2] - nm1);
                sc[nt][3] = __expf(sc[nt][3] - nm1);
                sum0 += sc[nt][0] + sc[nt][1];
                sum1 += sc[nt][2] + sc[nt][3];
            }
            sum0 += __shfl_xor_sync(0xffffffffu, sum0, 1);
            sum0 += __shfl_xor_sync(0xffffffffu, sum0, 2);
            sum1 += __shfl_xor_sync(0xffffffffu, sum1, 1);
            sum1 += __shfl_xor_sync(0xffffffffu, sum1, 2);
            lrow[mt][0] = lrow[mt][0] * corr0 + sum0;
            lrow[mt][1] = lrow[mt][1] * corr1 + sum1;

            #pragma unroll
            for (int nt = 0; nt < 8; ++nt) {
                o[mt][nt][0] *= corr0;
                o[mt][nt][1] *= corr0;
                o[mt][nt][2] *= corr1;
                o[mt][nt][3] *= corr1;
            }

            // ---- O += P V (split bf16, 3 products)
            #pragma unroll
            for (int kv = 0; kv < 4; ++kv) {
                uint32_t ph[4], pl[4];
                #pragma unroll
                for (int half = 0; half < 2; ++half) {
                    const float* f = sc[2 * kv + half];
                    __nv_bfloat16 h0 = __float2bfloat16(f[0]);
                    __nv_bfloat16 h1 = __float2bfloat16(f[1]);
                    __nv_bfloat16 h2 = __float2bfloat16(f[2]);
                    __nv_bfloat16 h3 = __float2bfloat16(f[3]);
                    ph[2 * half]     = ((uint32_t)__bfloat16_as_ushort(h1) << 16) |
                                       __bfloat16_as_ushort(h0);
                    ph[2 * half + 1] = ((uint32_t)__bfloat16_as_ushort(h3) << 16) |
                                       __bfloat16_as_ushort(h2);
                    pl[2 * half]     = packbf(f[0] - __bfloat162float(h0),
                                              f[1] - __bfloat162float(h1));
                    pl[2 * half + 1] = packbf(f[2] - __bfloat162float(h2),
                                              f[3] - __bfloat162float(h3));
                }
                #pragma unroll
                for (int np = 0; np < 4; ++np) {
                    uint32_t voff = (uint32_t)((s0 + kv * 16 + vRow) * AST + np * 16 + vCol);
                    uint32_t vh[4], vl[4];
                    ldsm4t(vh, sb + (V_HI + voff) * 2);
                    ldsm4t(vl, sb + (V_LO + voff) * 2);
                    mma16816(o[mt][2 * np],     ph, vh[0], vh[1]);
                    mma16816(o[mt][2 * np],     ph, vl[0], vl[1]);
                    mma16816(o[mt][2 * np],     pl, vh[0], vh[1]);
                    mma16816(o[mt][2 * np + 1], ph, vh[2], vh[3]);
                    mma16816(o[mt][2 * np + 1], ph, vl[2], vl[3]);
                    mma16816(o[mt][2 * np + 1], pl, vh[2], vh[3]);
                }
            }
        }
    }

    // ---- write out
    #pragma unroll
    for (int mt = 0; mt < 2; ++mt) {
        const int r0 = Rb[mt] + t4;
        const float inv0 = 1.f / lrow[mt][0];
        const float inv1 = 1.f / lrow[mt][1];
        #pragma unroll
        for (int nt = 0; nt < 8; ++nt) {
            int col = 8 * nt + 2 * tg;
            size_t o0 = ((size_t)b * TT + r0) * HH + col;
            *(float2*)(out + o0)           = make_float2(o[mt][nt][0] * inv0,
                                                         o[mt][nt][1] * inv0);
            *(float2*)(out + o0 + 8 * HH)  = make_float2(o[mt][nt][2] * inv1,
                                                         o[mt][nt][3] * inv1);
        }
    }
}

// ---------------------------------------------------------------------------
extern "C" void kernel_launch(void* const* d_in, const int* in_sizes, int n_in,
                              void* d_out, int out_size)
{
    const float* x  = (const float*)d_in[0];
    const float* Wq = (const float*)d_in[1];
    const float* Wk = (const float*)d_in[2];
    const float* Wv = (const float*)d_in[3];
    float* out = (float*)d_out;

    cudaFuncSetAttribute(proj_mma_kernel,
                         cudaFuncAttributeMaxDynamicSharedMemorySize, PROJ_SMEM);
    cudaFuncSetAttribute(attn_mma_kernel,
                         cudaFuncAttributeMaxDynamicSharedMemorySize, ATTN_SMEM);

    wsplit_kernel<<<(192 * 384 + 255) / 256, 256>>>(Wq, Wk, Wv);
    proj_mma_kernel<<<MTOT / 128, 512, PROJ_SMEM>>>(x);
    attn_mma_kernel<<<BB, 256, ATTN_SMEM>>>(out);
}

// round 7
// speedup vs baseline: 2.6121x; 1.0476x over previous
#include <cuda_runtime.h>
#include <cuda_bf16.h>
#include <math.h>
#include <stdint.h>

#define BB   256
#define TT   256
#define DD   384
#define HH   64
#define MTOT (BB*TT)                       // 65536 rows
#define HEADELEMS ((size_t)MTOT*HH)

// scratch: q,k,v split bf16 hi/lo + split weights (transposed [n][k], bf16)
__device__ __nv_bfloat16 g_h[3 * (size_t)MTOT * HH];
__device__ __nv_bfloat16 g_l[3 * (size_t)MTOT * HH];
__device__ __nv_bfloat16 g_wh[192 * 384];
__device__ __nv_bfloat16 g_wl[192 * 384];

// ---------------------------------------------------------------------------
__device__ __forceinline__ uint32_t smem_u32(const void* p) {
    uint32_t a;
    asm("{ .reg .u64 t; cvta.to.shared.u64 t, %1; cvt.u32.u64 %0, t; }"
        : "=r"(a) : "l"(p));
    return a;
}

__device__ __forceinline__ void ldsm4(uint32_t r[4], uint32_t addr) {
    asm volatile("ldmatrix.sync.aligned.m8n8.x4.shared.b16 {%0,%1,%2,%3}, [%4];"
                 : "=r"(r[0]), "=r"(r[1]), "=r"(r[2]), "=r"(r[3]) : "r"(addr));
}

__device__ __forceinline__ void ldsm4t(uint32_t r[4], uint32_t addr) {
    asm volatile("ldmatrix.sync.aligned.m8n8.x4.trans.shared.b16 {%0,%1,%2,%3}, [%4];"
                 : "=r"(r[0]), "=r"(r[1]), "=r"(r[2]), "=r"(r[3]) : "r"(addr));
}

__device__ __forceinline__ void mma16816(float c[4], const uint32_t a[4],
                                         uint32_t b0, uint32_t b1) {
    asm volatile(
        "mma.sync.aligned.m16n8k16.row.col.f32.bf16.bf16.f32 "
        "{%0,%1,%2,%3}, {%4,%5,%6,%7}, {%8,%9}, {%0,%1,%2,%3};"
        : "+f"(c[0]), "+f"(c[1]), "+f"(c[2]), "+f"(c[3])
        : "r"(a[0]), "r"(a[1]), "r"(a[2]), "r"(a[3]), "r"(b0), "r"(b1));
}

// pack two f32 -> bf16x2 (first arg in low half)
__device__ __forceinline__ uint32_t packbf(float lo, float hi) {
    uint32_t r;
    asm("cvt.rn.bf16x2.f32 %0, %1, %2;" : "=r"(r) : "f"(hi), "f"(lo));
    return r;
}

__device__ __forceinline__ void cpasync16(uint32_t dst, const void* src) {
    asm volatile("cp.async.cg.shared.global [%0], [%1], 16;"
                 :: "r"(dst), "l"(src));
}

// ---------------------------------------------------------------------------
// Weight split prep: smem-tiled transpose, coalesced loads AND stores.
// grid = 3 weights * 6 k-tiles; 256 threads.
// ---------------------------------------------------------------------------
__global__ void wsplit_kernel(const float* __restrict__ Wq,
                              const float* __restrict__ Wk,
                              const float* __restrict__ Wv) {
    __shared__ float ws[64][65];
    const int sel = blockIdx.x / 6;
    const int k0  = (blockIdx.x % 6) * 64;
    const float* W = (sel == 0) ? Wq : (sel == 1) ? Wk : Wv;
    const int tid = threadIdx.x;

    #pragma unroll
    for (int it = 0; it < 16; ++it) {
        int idx = tid + it * 256;          // 0..4095
        int k = idx >> 6, n = idx & 63;
        ws[k][n] = W[(size_t)(k0 + k) * HH + n];
    }
    __syncthreads();
    #pragma unroll
    for (int it = 0; it < 16; ++it) {
        int idx = tid + it * 256;
        int n = idx >> 6, k = idx & 63;
        float v = ws[k][n];
        __nv_bfloat16 h = __float2bfloat16(v);
        size_t o = (size_t)(sel * 64 + n) * DD + k0 + k;
        g_wh[o] = h;
        g_wl[o] = __float2bfloat16(v - __bfloat162float(h));
    }
}

// ---------------------------------------------------------------------------
// Pipelined mma.sync projection. M-tile 64, 256 threads, 2 CTAs/SM (80KB smem).
// A: fp32 x -> LDG -> convert -> STS, stride 40 halves, double buf.
// B: cp.async bf16 from g_wh/g_wl, stride 40 halves, double buf.
// ---------------------------------------------------------------------------
#define KC    32
#define KS    40
#define ABUFH 2560     // halves: 64*40 per array
#define B_BASE 10240   // halves: 2 bufs * 2 arrays * 2560
#define BBUFH 7680     // halves: 192*40 per array
#define PROJ_SMEM ((10240 + 30720) * 2)   // 81920 bytes

__global__ void __launch_bounds__(256, 2) proj_mma_kernel(const float* __restrict__ x)
{
    extern __shared__ __nv_bfloat16 sm[];
    const uint32_t sb = smem_u32(sm);
    const int tid  = threadIdx.x;
    const int lane = tid & 31;
    const int wid  = tid >> 5;
    const int wm   = wid & 1;        // 2 m-blocks of 32 rows
    const int wn   = wid >> 1;       // 4 n-blocks of 48 cols
    const int m0   = blockIdx.x * 64;

    const int aRow = (lane & 7) + ((lane >> 3) & 1) * 8;
    const int aCol = ((lane >> 4) & 1) * 8;
    const int bN   = (lane & 7) + ((lane >> 4) & 1) * 8;
    const int bK   = ((lane >> 3) & 1) * 8;

    float c[2][6][4];
    #pragma unroll
    for (int mt = 0; mt < 2; ++mt)
        #pragma unroll
        for (int nt = 0; nt < 6; ++nt)
            #pragma unroll
            for (int j = 0; j < 4; ++j) c[mt][nt][j] = 0.f;

    float4 aCur[2], aNxt[2];

    // ---- prologue: B(0) cp.async -> buf0, A(0) -> regs
    {
        #pragma unroll
        for (int it = 0; it < 6; ++it) {
            int idx = tid + it * 256;              // 0..1535
            int sub = (idx < 768) ? idx : idx - 768;
            int n   = sub >> 2;
            int kg  = (sub & 3) * 8;
            const __nv_bfloat16* src =
                ((idx < 768) ? g_wh : g_wl) + (size_t)n * DD + kg;
            uint32_t dst = sb + (uint32_t)(B_BASE + ((idx < 768) ? 0 : BBUFH) +
                                           n * KS + kg) * 2;
            cpasync16(dst, src);
        }
        asm volatile("cp.async.commit_group;" ::: "memory");
        #pragma unroll
        for (int it = 0; it < 2; ++it) {
            int idx = tid + it * 256;              // 0..511 float4s
            int r = idx >> 3, c4 = (idx & 7) * 4;
            aCur[it] = *(const float4*)(x + (size_t)(m0 + r) * DD + c4);
        }
    }

    int p = 0;
    #pragma unroll 1
    for (int ch = 0; ch < 12; ++ch) {
        // ---- STS A(ch) into bufA[p] (convert fp32 -> hi/lo bf16)
        #pragma unroll
        for (int it = 0; it < 2; ++it) {
            int idx = tid + it * 256;
            int r = idx >> 3, c4 = (idx & 7) * 4;
            float4 v = aCur[it];
            __nv_bfloat16 h0 = __float2bfloat16(v.x);
            __nv_bfloat16 h1 = __float2bfloat16(v.y);
            __nv_bfloat16 h2 = __float2bfloat16(v.z);
            __nv_bfloat16 h3 = __float2bfloat16(v.w);
            uint32_t hp0 = ((uint32_t)__bfloat16_as_ushort(h1) << 16) | __bfloat16_as_ushort(h0);
            uint32_t hp1 = ((uint32_t)__bfloat16_as_ushort(h3) << 16) | __bfloat16_as_ushort(h2);
            uint32_t lp0 = packbf(v.x - __bfloat162float(h0), v.y - __bfloat162float(h1));
            uint32_t lp1 = packbf(v.z - __bfloat162float(h2), v.w - __bfloat162float(h3));
            int off = p * 5120 + r * KS + c4;
            *(uint2*)(sm + off)         = make_uint2(hp0, hp1);
            *(uint2*)(sm + off + ABUFH) = make_uint2(lp0, lp1);
        }

        // ---- drain B(ch), barrier
        asm volatile("cp.async.wait_group 0;" ::: "memory");
        __syncthreads();

        // ---- issue B(ch+1) + LDG A(ch+1); overlaps the MMA phase below
        if (ch < 11) {
            const int k1 = (ch + 1) * KC;
            #pragma unroll
            for (int it = 0; it < 6; ++it) {
                int idx = tid + it * 256;
                int sub = (idx < 768) ? idx : idx - 768;
                int n   = sub >> 2;
                int kg  = (sub & 3) * 8;
                const __nv_bfloat16* src =
                    ((idx < 768) ? g_wh : g_wl) + (size_t)n * DD + k1 + kg;
                uint32_t dst = sb + (uint32_t)(B_BASE + (p ^ 1) * 15360 +
                                               ((idx < 768) ? 0 : BBUFH) +
                                               n * KS + kg) * 2;
                cpasync16(dst, src);
            }
            asm volatile("cp.async.commit_group;" ::: "memory");
            #pragma unroll
            for (int it = 0; it < 2; ++it) {
                int idx = tid + it * 256;
                int r = idx >> 3, c4 = (idx & 7) * 4;
                aNxt[it] = *(const float4*)(x + (size_t)(m0 + r) * DD + k1 + c4);
            }
        }

        // ---- MMA over buffers p
        const uint32_t aBase = (uint32_t)(p * 5120);
        const uint32_t bBase = (uint32_t)(B_BASE + p * 15360);
        #pragma unroll
        for (int ks = 0; ks < 2; ++ks) {
            const int kk = ks * 16;
            uint32_t ah[2][4], al[2][4];
            #pragma unroll
            for (int mt = 0; mt < 2; ++mt) {
                uint32_t off = (uint32_t)((wm * 32 + mt * 16 + aRow) * KS + kk + aCol);
                ldsm4(ah[mt], sb + (aBase + off) * 2);
                ldsm4(al[mt], sb + (aBase + ABUFH + off) * 2);
            }
            #pragma unroll
            for (int np = 0; np < 3; ++np) {
                uint32_t boff = (uint32_t)((wn * 48 + np * 16 + bN) * KS + kk + bK);
                uint32_t bh[4], bl[4];
                ldsm4(bh, sb + (bBase + boff) * 2);
                ldsm4(bl, sb + (bBase + BBUFH + boff) * 2);
                #pragma unroll
                for (int mt = 0; mt < 2; ++mt)
                    #pragma unroll
                    for (int sub = 0; sub < 2; ++sub) {
                        float* cc = c[mt][sub + np * 2];
                        mma16816(cc, ah[mt], bh[sub * 2], bh[sub * 2 + 1]);
                        mma16816(cc, ah[mt], bl[sub * 2], bl[sub * 2 + 1]);
                        mma16816(cc, al[mt], bh[sub * 2], bh[sub * 2 + 1]);
                    }
            }
        }

        aCur[0] = aNxt[0];
        aCur[1] = aNxt[1];
        p ^= 1;
    }

    // ---- epilogue: fp32 acc -> hi/lo bf16 to g_h/g_l (q pre-scaled by 0.125)
    const int t4 = lane >> 2;
    const int c2 = (lane & 3) * 2;
    #pragma unroll
    for (int mt = 0; mt < 2; ++mt)
        #pragma unroll
        for (int nt = 0; nt < 6; ++nt) {
            int col = wn * 48 + nt * 8 + c2;
            int sel = col >> 6;
            int hc  = col & 63;
            float s = (sel == 0) ? 0.125f : 1.0f;
            float v0 = c[mt][nt][0] * s, v1 = c[mt][nt][1] * s;
            float v2 = c[mt][nt][2] * s, v3 = c[mt][nt][3] * s;
            __nv_bfloat16 h0 = __float2bfloat16(v0);
            __nv_bfloat16 h1 = __float2bfloat16(v1);
            __nv_bfloat16 h2 = __float2bfloat16(v2);
            __nv_bfloat16 h3 = __float2bfloat16(v3);
            size_t base = (size_t)sel * HEADELEMS +
                          (size_t)(m0 + wm * 32 + mt * 16 + t4) * HH + hc;
            *(uint32_t*)(g_h + base) =
                ((uint32_t)__bfloat16_as_ushort(h1) << 16) | __bfloat16_as_ushort(h0);
            *(uint32_t*)(g_h + base + 8 * HH) =
                ((uint32_t)__bfloat16_as_ushort(h3) << 16) | __bfloat16_as_ushort(h2);
            *(uint32_t*)(g_l + base) =
                packbf(v0 - __bfloat162float(h0), v1 - __bfloat162float(h1));
            *(uint32_t*)(g_l + base + 8 * HH) =
                packbf(v2 - __bfloat162float(h2), v3 - __bfloat162float(h3));
        }
}

// ---------------------------------------------------------------------------
// Tensor-core flash attention. One CTA per batch, 8 warps.
// Causal np/kv tile skip in the diagonal chunk (bit-identical output).
// ---------------------------------------------------------------------------
#define AST 72
#define Q_HI 0
#define Q_LO (256*AST)
#define K_HI (2*256*AST)
#define K_LO (3*256*AST)
#define V_HI (4*256*AST)
#define V_LO (5*256*AST)
#define ATTN_SMEM (6*256*AST*2)    // 221184 bytes

__global__ void __launch_bounds__(256, 1) attn_mma_kernel(float* __restrict__ out)
{
    extern __shared__ __nv_bfloat16 asmem[];
    const uint32_t sb = smem_u32(asmem);
    const int b    = blockIdx.x;
    const int tid  = threadIdx.x;
    const int lane = tid & 31;
    const int w    = tid >> 5;
    const int t4   = lane >> 2;
    const int tg   = lane & 3;

    // ---- cp.async load: 6 arrays (q/k/v hi,lo) of [256][64] bf16 -> stride-72 smem
    #pragma unroll
    for (int it = 0; it < 48; ++it) {
        int idx = tid + it * 256;              // 0..12287
        int arr = idx >> 11;                   // 0..5: q_hi,q_lo,k_hi,k_lo,v_hi,v_lo
        int rem = idx & 2047;
        int r   = rem >> 3;
        int kg  = (rem & 7) * 8;
        const __nv_bfloat16* src = ((arr & 1) ? g_l : g_h) +
            (size_t)(arr >> 1) * HEADELEMS + ((size_t)b * TT + r) * HH + kg;
        uint32_t dst = sb + (uint32_t)(arr * 256 * AST + r * AST + kg) * 2;
        cpasync16(dst, src);
    }
    asm volatile("cp.async.commit_group;\n\tcp.async.wait_group 0;" ::: "memory");
    __syncthreads();

    const int Rb[2] = { 16 * w, 240 - 16 * w };

    float o[2][8][4];
    float mrow[2][2], lrow[2][2];
    #pragma unroll
    for (int mt = 0; mt < 2; ++mt) {
        mrow[mt][0] = mrow[mt][1] = -1e30f;
        lrow[mt][0] = lrow[mt][1] = 0.f;
        #pragma unroll
        for (int nt = 0; nt < 8; ++nt)
            #pragma unroll
            for (int j = 0; j < 4; ++j) o[mt][nt][j] = 0.f;
    }

    const int qRow = lane & 15;
    const int qCol = ((lane >> 4) & 1) * 8;
    const int kRow = (lane & 7) + ((lane >> 4) & 1) * 8;
    const int kCol = ((lane >> 3) & 1) * 8;
    const int vRow = lane & 15;
    const int vCol = ((lane >> 4) & 1) * 8;

    #pragma unroll 1
    for (int s0 = 0; s0 < TT; s0 += 64) {
        #pragma unroll
        for (int mt = 0; mt < 2; ++mt) {
            const int base = Rb[mt];
            if (s0 > base + 15) continue;

            // tiles with col-start > base+15 are fully masked: skip their MMAs
            const int npMax = min(4, ((base + 15 - s0) >> 4) + 1);

            // ---- S = Q K^T (split bf16, 3 products)
            float sc[8][4];
            #pragma unroll
            for (int nt = 0; nt < 8; ++nt)
                #pragma unroll
                for (int j = 0; j < 4; ++j) sc[nt][j] = 0.f;

            #pragma unroll
            for (int kc = 0; kc < 4; ++kc) {
                uint32_t qh[4], ql[4];
                uint32_t qoff = (uint32_t)((base + qRow) * AST + kc * 16 + qCol);
                ldsm4(qh, sb + (Q_HI + qoff) * 2);
                ldsm4(ql, sb + (Q_LO + qoff) * 2);
                #pragma unroll
                for (int np = 0; np < 4; ++np) {
                    if (np < npMax) {
                        uint32_t koff = (uint32_t)((s0 + np * 16 + kRow) * AST + kc * 16 + kCol);
                        uint32_t kh[4], kl[4];
                        ldsm4(kh, sb + (K_HI + koff) * 2);
                        ldsm4(kl, sb + (K_LO + koff) * 2);
                        mma16816(sc[2 * np],     qh, kh[0], kh[1]);
                        mma16816(sc[2 * np],     qh, kl[0], kl[1]);
                        mma16816(sc[2 * np],     ql, kh[0], kh[1]);
                        mma16816(sc[2 * np + 1], qh, kh[2], kh[3]);
                        mma16816(sc[2 * np + 1], qh, kl[2], kl[3]);
                        mma16816(sc[2 * np + 1], ql, kh[2], kh[3]);
                    }
                }
            }

            // ---- causal mask + online softmax
            const int r0 = base + t4;
            const int r1 = r0 + 8;
            #pragma unroll
            for (int nt = 0; nt < 8; ++nt) {
                int col = s0 + 8 * nt + 2 * tg;
                if (col     > r0) sc[nt][0] = -1e30f;
                if (col + 1 > r0) sc[nt][1] = -1e30f;
                if (col     > r1) sc[nt][2] = -1e30f;
                if (col + 1 > r1) sc[nt][3] = -1e30f;
            }
            float mx0 = sc[0][0], mx1 = sc[0][2];
            #pragma unroll
            for (int nt = 0; nt < 8; ++nt) {
                mx0 = fmaxf(mx0, fmaxf(sc[nt][0], sc[nt][1]));
                mx1 = fmaxf(mx1, fmaxf(sc[nt][2], sc[nt][3]));
            }
            mx0 = fmaxf(mx0, __shfl_xor_sync(0xffffffffu, mx0, 1));
            mx0 = fmaxf(mx0, __shfl_xor_sync(0xffffffffu, mx0, 2));
            mx1 = fmaxf(mx1, __shfl_xor_sync(0xffffffffu, mx1, 1));
            mx1 = fmaxf(mx1, __shfl_xor_sync(0xffffffffu, mx1, 2));

            float nm0 = fmaxf(mrow[mt][0], mx0);
            float nm1 = fmaxf(mrow[mt][1], mx1);
            float corr0 = __expf(mrow[mt][0] - nm0);
            float corr1 = __expf(mrow[mt][1] - nm1);
            mrow[mt][0] = nm0;
            mrow[mt][1] = nm1;

            float sum0 = 0.f, sum1 = 0.f;
            #pragma unroll
            for (int nt = 0; nt < 8; ++nt) {
                sc[nt][0] = __expf(sc[nt][0] - nm0);
                sc[nt][1] = __expf(sc[nt][1] - nm0);
                sc[nt][2] = __expf(sc[nt][2] - nm1);
                sc[nt][3] = __expf(sc[nt][3] - nm1);
                sum0 += sc[nt][0] + sc[nt][1];
                sum1 += sc[nt][2] + sc[nt][3];
            }
            sum0 += __shfl_xor_sync(0xffffffffu, sum0, 1);
            sum0 += __shfl_xor_sync(0xffffffffu, sum0, 2);
            sum1 += __shfl_xor_sync(0xffffffffu, sum1, 1);
            sum1 += __shfl_xor_sync(0xffffffffu, sum1, 2);
            lrow[mt][0] = lrow[mt][0] * corr0 + sum0;
            lrow[mt][1] = lrow[mt][1] * corr1 + sum1;

            #pragma unroll
            for (int nt = 0; nt < 8; ++nt) {
                o[mt][nt][0] *= corr0;
                o[mt][nt][1] *= corr0;
                o[mt][nt][2] *= corr1;
                o[mt][nt][3] *= corr1;
            }

            // ---- O += P V (split bf16, 3 products); skip all-zero P tiles
            #pragma unroll
            for (int kv = 0; kv < 4; ++kv) {
                if (kv < npMax) {
                    uint32_t ph[4], pl[4];
                    #pragma unroll
                    for (int half = 0; half < 2; ++half) {
                        const float* f = sc[2 * kv + half];
                        __nv_bfloat16 h0 = __float2bfloat16(f[0]);
                        __nv_bfloat16 h1 = __float2bfloat16(f[1]);
                        __nv_bfloat16 h2 = __float2bfloat16(f[2]);
                        __nv_bfloat16 h3 = __float2bfloat16(f[3]);
                        ph[2 * half]     = ((uint32_t)__bfloat16_as_ushort(h1) << 16) |
                                           __bfloat16_as_ushort(h0);
                        ph[2 * half + 1] = ((uint32_t)__bfloat16_as_ushort(h3) << 16) |
                                           __bfloat16_as_ushort(h2);
                        pl[2 * half]     = packbf(f[0] - __bfloat162float(h0),
                                                  f[1] - __bfloat162float(h1));
                        pl[2 * half + 1] = packbf(f[2] - __bfloat162float(h2),
                                                  f[3] - __bfloat162float(h3));
                    }
                    #pragma unroll
                    for (int np = 0; np < 4; ++np) {
                        uint32_t voff = (uint32_t)((s0 + kv * 16 + vRow) * AST + np * 16 + vCol);
                        uint32_t vh[4], vl[4];
                        ldsm4t(vh, sb + (V_HI + voff) * 2);
                        ldsm4t(vl, sb + (V_LO + voff) * 2);
                        mma16816(o[mt][2 * np],     ph, vh[0], vh[1]);
                        mma16816(o[mt][2 * np],     ph, vl[0], vl[1]);
                        mma16816(o[mt][2 * np],     pl, vh[0], vh[1]);
                        mma16816(o[mt][2 * np + 1], ph, vh[2], vh[3]);
                        mma16816(o[mt][2 * np + 1], ph, vl[2], vl[3]);
                        mma16816(o[mt][2 * np + 1], pl, vh[2], vh[3]);
                    }
                }
            }
        }
    }

    // ---- write out
    #pragma unroll
    for (int mt = 0; mt < 2; ++mt) {
        const int r0 = Rb[mt] + t4;
        const float inv0 = 1.f / lrow[mt][0];
        const float inv1 = 1.f / lrow[mt][1];
        #pragma unroll
        for (int nt = 0; nt < 8; ++nt) {
            int col = 8 * nt + 2 * tg;
            size_t o0 = ((size_t)b * TT + r0) * HH + col;
            *(float2*)(out + o0)           = make_float2(o[mt][nt][0] * inv0,
                                                         o[mt][nt][1] * inv0);
            *(float2*)(out + o0 + 8 * HH)  = make_float2(o[mt][nt][2] * inv1,
                                                         o[mt][nt][3] * inv1);
        }
    }
}

// ---------------------------------------------------------------------------
extern "C" void kernel_launch(void* const* d_in, const int* in_sizes, int n_in,
                              void* d_out, int out_size)
{
    const float* x  = (const float*)d_in[0];
    const float* Wq = (const float*)d_in[1];
    const float* Wk = (const float*)d_in[2];
    const float* Wv = (const float*)d_in[3];
    float* out = (float*)d_out;

    cudaFuncSetAttribute(proj_mma_kernel,
                         cudaFuncAttributeMaxDynamicSharedMemorySize, PROJ_SMEM);
    cudaFuncSetAttribute(attn_mma_kernel,
                         cudaFuncAttributeMaxDynamicSharedMemorySize, ATTN_SMEM);

    wsplit_kernel<<<18, 256>>>(Wq, Wk, Wv);
    proj_mma_kernel<<<MTOT / 64, 256, PROJ_SMEM>>>(x);
    attn_mma_kernel<<<BB, 256, ATTN_SMEM>>>(out);
}

// round 8
// speedup vs baseline: 2.8776x; 1.1017x over previous
#include <cuda_runtime.h>
#include <cuda_bf16.h>
#include <cuda_fp16.h>
#include <math.h>
#include <stdint.h>

#define BB   256
#define TT   256
#define DD   384
#define HH   64
#define MTOT (BB*TT)                       // 65536 rows
#define HEADELEMS ((size_t)MTOT*HH)

// scratch: q,k,v split fp16 hi/lo (attn operands) + split weights (bf16, proj)
__device__ __half g_h[3 * (size_t)MTOT * HH];
__device__ __half g_l[3 * (size_t)MTOT * HH];
__device__ __nv_bfloat16 g_wh[192 * 384];
__device__ __nv_bfloat16 g_wl[192 * 384];

// ---------------------------------------------------------------------------
__device__ __forceinline__ uint32_t smem_u32(const void* p) {
    uint32_t a;
    asm("{ .reg .u64 t; cvta.to.shared.u64 t, %1; cvt.u32.u64 %0, t; }"
        : "=r"(a) : "l"(p));
    return a;
}

__device__ __forceinline__ void ldsm4(uint32_t r[4], uint32_t addr) {
    asm volatile("ldmatrix.sync.aligned.m8n8.x4.shared.b16 {%0,%1,%2,%3}, [%4];"
                 : "=r"(r[0]), "=r"(r[1]), "=r"(r[2]), "=r"(r[3]) : "r"(addr));
}

__device__ __forceinline__ void ldsm4t(uint32_t r[4], uint32_t addr) {
    asm volatile("ldmatrix.sync.aligned.m8n8.x4.trans.shared.b16 {%0,%1,%2,%3}, [%4];"
                 : "=r"(r[0]), "=r"(r[1]), "=r"(r[2]), "=r"(r[3]) : "r"(addr));
}

// bf16 mma (projection)
__device__ __forceinline__ void mma16816(float c[4], const uint32_t a[4],
                                         uint32_t b0, uint32_t b1) {
    asm volatile(
        "mma.sync.aligned.m16n8k16.row.col.f32.bf16.bf16.f32 "
        "{%0,%1,%2,%3}, {%4,%5,%6,%7}, {%8,%9}, {%0,%1,%2,%3};"
        : "+f"(c[0]), "+f"(c[1]), "+f"(c[2]), "+f"(c[3])
        : "r"(a[0]), "r"(a[1]), "r"(a[2]), "r"(a[3]), "r"(b0), "r"(b1));
}

// fp16 mma (attention)
__device__ __forceinline__ void mma16816h(float c[4], const uint32_t a[4],
                                          uint32_t b0, uint32_t b1) {
    asm volatile(
        "mma.sync.aligned.m16n8k16.row.col.f32.f16.f16.f32 "
        "{%0,%1,%2,%3}, {%4,%5,%6,%7}, {%8,%9}, {%0,%1,%2,%3};"
        : "+f"(c[0]), "+f"(c[1]), "+f"(c[2]), "+f"(c[3])
        : "r"(a[0]), "r"(a[1]), "r"(a[2]), "r"(a[3]), "r"(b0), "r"(b1));
}

// pack two f32 -> bf16x2 (first arg in low half)
__device__ __forceinline__ uint32_t packbf(float lo, float hi) {
    uint32_t r;
    asm("cvt.rn.bf16x2.f32 %0, %1, %2;" : "=r"(r) : "f"(hi), "f"(lo));
    return r;
}

// pack two f32 -> f16x2 (first arg in low half)
__device__ __forceinline__ uint32_t packhf(float lo, float hi) {
    __half2 h = __floats2half2_rn(lo, hi);
    return *(uint32_t*)&h;
}

__device__ __forceinline__ void cpasync16(uint32_t dst, const void* src) {
    asm volatile("cp.async.cg.shared.global [%0], [%1], 16;"
                 :: "r"(dst), "l"(src));
}

// ---------------------------------------------------------------------------
// Weight split prep: smem-tiled transpose, 36 blocks (3 sel x 12 k-tiles of 32)
// ---------------------------------------------------------------------------
__global__ void wsplit_kernel(const float* __restrict__ Wq,
                              const float* __restrict__ Wk,
                              const float* __restrict__ Wv) {
    __shared__ float ws[32][65];
    const int sel = blockIdx.x / 12;
    const int k0  = (blockIdx.x % 12) * 32;
    const float* W = (sel == 0) ? Wq : (sel == 1) ? Wk : Wv;
    const int tid = threadIdx.x;

    #pragma unroll
    for (int it = 0; it < 8; ++it) {
        int idx = tid + it * 256;          // 0..2047
        int k = idx >> 6, n = idx & 63;
        ws[k][n] = W[(size_t)(k0 + k) * HH + n];
    }
    __syncthreads();
    #pragma unroll
    for (int it = 0; it < 8; ++it) {
        int idx = tid + it * 256;
        int n = idx >> 5, k = idx & 31;
        float v = ws[k][n];
        __nv_bfloat16 h = __float2bfloat16(v);
        size_t o = (size_t)(sel * 64 + n) * DD + k0 + k;
        g_wh[o] = h;
        g_wl[o] = __float2bfloat16(v - __bfloat162float(h));
    }
}

// ---------------------------------------------------------------------------
// Pipelined mma.sync projection (unchanged structure from R7).
// ---------------------------------------------------------------------------
#define KC    32
#define KS    40
#define ABUFH 2560     // halves: 64*40 per array
#define B_BASE 10240   // halves
#define BBUFH 7680     // halves: 192*40 per array
#define PROJ_SMEM ((10240 + 30720) * 2)   // 81920 bytes

__global__ void __launch_bounds__(256, 2) proj_mma_kernel(const float* __restrict__ x)
{
    extern __shared__ __nv_bfloat16 sm[];
    const uint32_t sb = smem_u32(sm);
    const int tid  = threadIdx.x;
    const int lane = tid & 31;
    const int wid  = tid >> 5;
    const int wm   = wid & 1;
    const int wn   = wid >> 1;
    const int m0   = blockIdx.x * 64;

    const int aRow = (lane & 7) + ((lane >> 3) & 1) * 8;
    const int aCol = ((lane >> 4) & 1) * 8;
    const int bN   = (lane & 7) + ((lane >> 4) & 1) * 8;
    const int bK   = ((lane >> 3) & 1) * 8;

    float c[2][6][4];
    #pragma unroll
    for (int mt = 0; mt < 2; ++mt)
        #pragma unroll
        for (int nt = 0; nt < 6; ++nt)
            #pragma unroll
            for (int j = 0; j < 4; ++j) c[mt][nt][j] = 0.f;

    float4 aCur[2], aNxt[2];

    {
        #pragma unroll
        for (int it = 0; it < 6; ++it) {
            int idx = tid + it * 256;
            int sub = (idx < 768) ? idx : idx - 768;
            int n   = sub >> 2;
            int kg  = (sub & 3) * 8;
            const __nv_bfloat16* src =
                ((idx < 768) ? g_wh : g_wl) + (size_t)n * DD + kg;
            uint32_t dst = sb + (uint32_t)(B_BASE + ((idx < 768) ? 0 : BBUFH) +
                                           n * KS + kg) * 2;
            cpasync16(dst, src);
        }
        asm volatile("cp.async.commit_group;" ::: "memory");
        #pragma unroll
        for (int it = 0; it < 2; ++it) {
            int idx = tid + it * 256;
            int r = idx >> 3, c4 = (idx & 7) * 4;
            aCur[it] = *(const float4*)(x + (size_t)(m0 + r) * DD + c4);
        }
    }

    int p = 0;
    #pragma unroll 1
    for (int ch = 0; ch < 12; ++ch) {
        #pragma unroll
        for (int it = 0; it < 2; ++it) {
            int idx = tid + it * 256;
            int r = idx >> 3, c4 = (idx & 7) * 4;
            float4 v = aCur[it];
            __nv_bfloat16 h0 = __float2bfloat16(v.x);
            __nv_bfloat16 h1 = __float2bfloat16(v.y);
            __nv_bfloat16 h2 = __float2bfloat16(v.z);
            __nv_bfloat16 h3 = __float2bfloat16(v.w);
            uint32_t hp0 = ((uint32_t)__bfloat16_as_ushort(h1) << 16) | __bfloat16_as_ushort(h0);
            uint32_t hp1 = ((uint32_t)__bfloat16_as_ushort(h3) << 16) | __bfloat16_as_ushort(h2);
            uint32_t lp0 = packbf(v.x - __bfloat162float(h0), v.y - __bfloat162float(h1));
            uint32_t lp1 = packbf(v.z - __bfloat162float(h2), v.w - __bfloat162float(h3));
            int off = p * 5120 + r * KS + c4;
            *(uint2*)(sm + off)         = make_uint2(hp0, hp1);
            *(uint2*)(sm + off + ABUFH) = make_uint2(lp0, lp1);
        }

        asm volatile("cp.async.wait_group 0;" ::: "memory");
        __syncthreads();

        if (ch < 11) {
            const int k1 = (ch + 1) * KC;
            #pragma unroll
            for (int it = 0; it < 6; ++it) {
                int idx = tid + it * 256;
                int sub = (idx < 768) ? idx : idx - 768;
                int n   = sub >> 2;
                int kg  = (sub & 3) * 8;
                const __nv_bfloat16* src =
                    ((idx < 768) ? g_wh : g_wl) + (size_t)n * DD + k1 + kg;
                uint32_t dst = sb + (uint32_t)(B_BASE + (p ^ 1) * 15360 +
                                               ((idx < 768) ? 0 : BBUFH) +
                                               n * KS + kg) * 2;
                cpasync16(dst, src);
            }
            asm volatile("cp.async.commit_group;" ::: "memory");
            #pragma unroll
            for (int it = 0; it < 2; ++it) {
                int idx = tid + it * 256;
                int r = idx >> 3, c4 = (idx & 7) * 4;
                aNxt[it] = *(const float4*)(x + (size_t)(m0 + r) * DD + k1 + c4);
            }
        }

        const uint32_t aBase = (uint32_t)(p * 5120);
        const uint32_t bBase = (uint32_t)(B_BASE + p * 15360);
        #pragma unroll
        for (int ks = 0; ks < 2; ++ks) {
            const int kk = ks * 16;
            uint32_t ah[2][4], al[2][4];
            #pragma unroll
            for (int mt = 0; mt < 2; ++mt) {
                uint32_t off = (uint32_t)((wm * 32 + mt * 16 + aRow) * KS + kk + aCol);
                ldsm4(ah[mt], sb + (aBase + off) * 2);
                ldsm4(al[mt], sb + (aBase + ABUFH + off) * 2);
            }
            #pragma unroll
            for (int np = 0; np < 3; ++np) {
                uint32_t boff = (uint32_t)((wn * 48 + np * 16 + bN) * KS + kk + bK);
                uint32_t bh[4], bl[4];
                ldsm4(bh, sb + (bBase + boff) * 2);
                ldsm4(bl, sb + (bBase + BBUFH + boff) * 2);
                #pragma unroll
                for (int mt = 0; mt < 2; ++mt)
                    #pragma unroll
                    for (int sub = 0; sub < 2; ++sub) {
                        float* cc = c[mt][sub + np * 2];
                        mma16816(cc, ah[mt], bh[sub * 2], bh[sub * 2 + 1]);
                        mma16816(cc, ah[mt], bl[sub * 2], bl[sub * 2 + 1]);
                        mma16816(cc, al[mt], bh[sub * 2], bh[sub * 2 + 1]);
                    }
            }
        }

        aCur[0] = aNxt[0];
        aCur[1] = aNxt[1];
        p ^= 1;
    }

    // ---- epilogue: fp32 acc -> fp16 hi/lo to g_h/g_l (q pre-scaled by 0.125;
    //      q_lo never read by attn -> skip its store)
    const int t4 = lane >> 2;
    const int c2 = (lane & 3) * 2;
    #pragma unroll
    for (int mt = 0; mt < 2; ++mt)
        #pragma unroll
        for (int nt = 0; nt < 6; ++nt) {
            int col = wn * 48 + nt * 8 + c2;
            int sel = col >> 6;
            int hc  = col & 63;
            float s = (sel == 0) ? 0.125f : 1.0f;
            float v0 = c[mt][nt][0] * s, v1 = c[mt][nt][1] * s;
            float v2 = c[mt][nt][2] * s, v3 = c[mt][nt][3] * s;
            __half2 hp01 = __floats2half2_rn(v0, v1);
            __half2 hp23 = __floats2half2_rn(v2, v3);
            size_t base = (size_t)sel * HEADELEMS +
                          (size_t)(m0 + wm * 32 + mt * 16 + t4) * HH + hc;
            *(uint32_t*)(g_h + base)          = *(uint32_t*)&hp01;
            *(uint32_t*)(g_h + base + 8 * HH) = *(uint32_t*)&hp23;
            if (sel != 0) {
                uint32_t lp01 = packhf(v0 - __low2float(hp01), v1 - __high2float(hp01));
                uint32_t lp23 = packhf(v2 - __low2float(hp23), v3 - __high2float(hp23));
                *(uint32_t*)(g_l + base)          = lp01;
                *(uint32_t*)(g_l + base + 8 * HH) = lp23;
            }
        }
}

// ---------------------------------------------------------------------------
// Tensor-core flash attention, fp16 2-product GEMMs.
// S = qh*kh + qh*kl ; O += ph*vh + ph*vl  (P rounded once to fp16).
// smem: q_hi, k_hi, k_lo, v_hi, v_lo (5 arrays, stride 72 halves).
// ---------------------------------------------------------------------------
#define AST 72
#define Q_HI 0
#define K_HI (256*AST)
#define K_LO (2*256*AST)
#define V_HI (3*256*AST)
#define V_LO (4*256*AST)
#define ATTN_SMEM (5*256*AST*2)    // 184320 bytes

__global__ void __launch_bounds__(256, 1) attn_mma_kernel(float* __restrict__ out)
{
    extern __shared__ __half asmem[];
    const uint32_t sb = smem_u32(asmem);
    const int b    = blockIdx.x;
    const int tid  = threadIdx.x;
    const int lane = tid & 31;
    const int w    = tid >> 5;
    const int t4   = lane >> 2;
    const int tg   = lane & 3;

    // ---- cp.async load: 5 arrays of [256][64] fp16 -> stride-72 smem
    {
        const __half* srcs[5] = { g_h,
                                  g_h + HEADELEMS, g_l + HEADELEMS,
                                  g_h + 2 * HEADELEMS, g_l + 2 * HEADELEMS };
        #pragma unroll
        for (int it = 0; it < 40; ++it) {
            const int arr = it >> 3;               // 8 iterations per array
            int rem = (tid + it * 256) - arr * 2048;
            int r   = rem >> 3;
            int kg  = (rem & 7) * 8;
            const __half* src = srcs[arr] + ((size_t)b * TT + r) * HH + kg;
            uint32_t dst = sb + (uint32_t)(arr * 256 * AST + r * AST + kg) * 2;
            cpasync16(dst, src);
        }
    }
    asm volatile("cp.async.commit_group;\n\tcp.async.wait_group 0;" ::: "memory");
    __syncthreads();

    const int Rb[2] = { 16 * w, 240 - 16 * w };

    float o[2][8][4];
    float mrow[2][2], lrow[2][2];
    #pragma unroll
    for (int mt = 0; mt < 2; ++mt) {
        mrow[mt][0] = mrow[mt][1] = -1e30f;
        lrow[mt][0] = lrow[mt][1] = 0.f;
        #pragma unroll
        for (int nt = 0; nt < 8; ++nt)
            #pragma unroll
            for (int j = 0; j < 4; ++j) o[mt][nt][j] = 0.f;
    }

    const int qRow = lane & 15;
    const int qCol = ((lane >> 4) & 1) * 8;
    const int kRow = (lane & 7) + ((lane >> 4) & 1) * 8;
    const int kCol = ((lane >> 3) & 1) * 8;
    const int vRow = lane & 15;
    const int vCol = ((lane >> 4) & 1) * 8;

    #pragma unroll 1
    for (int s0 = 0; s0 < TT; s0 += 64) {
        #pragma unroll
        for (int mt = 0; mt < 2; ++mt) {
            const int base = Rb[mt];
            if (s0 > base + 15) continue;

            const int npMax = min(4, ((base + 15 - s0) >> 4) + 1);

            // ---- S = Q K^T (fp16, 2 products: qh*kh + qh*kl)
            float sc[8][4];
            #pragma unroll
            for (int nt = 0; nt < 8; ++nt)
                #pragma unroll
                for (int j = 0; j < 4; ++j) sc[nt][j] = 0.f;

            #pragma unroll
            for (int kc = 0; kc < 4; ++kc) {
                uint32_t qh[4];
                uint32_t qoff = (uint32_t)((base + qRow) * AST + kc * 16 + qCol);
                ldsm4(qh, sb + (Q_HI + qoff) * 2);
                #pragma unroll
                for (int np = 0; np < 4; ++np) {
                    if (np < npMax) {
                        uint32_t koff = (uint32_t)((s0 + np * 16 + kRow) * AST + kc * 16 + kCol);
                        uint32_t kh[4], kl[4];
                        ldsm4(kh, sb + (K_HI + koff) * 2);
                        ldsm4(kl, sb + (K_LO + koff) * 2);
                        mma16816h(sc[2 * np],     qh, kh[0], kh[1]);
                        mma16816h(sc[2 * np],     qh, kl[0], kl[1]);
                        mma16816h(sc[2 * np + 1], qh, kh[2], kh[3]);
                        mma16816h(sc[2 * np + 1], qh, kl[2], kl[3]);
                    }
                }
            }

            // ---- causal mask + online softmax
            const int r0 = base + t4;
            const int r1 = r0 + 8;
            #pragma unroll
            for (int nt = 0; nt < 8; ++nt) {
                int col = s0 + 8 * nt + 2 * tg;
                if (col     > r0) sc[nt][0] = -1e30f;
                if (col + 1 > r0) sc[nt][1] = -1e30f;
                if (col     > r1) sc[nt][2] = -1e30f;
                if (col + 1 > r1) sc[nt][3] = -1e30f;
            }
            float mx0 = sc[0][0], mx1 = sc[0][2];
            #pragma unroll
            for (int nt = 0; nt < 8; ++nt) {
                mx0 = fmaxf(mx0, fmaxf(sc[nt][0], sc[nt][1]));
                mx1 = fmaxf(mx1, fmaxf(sc[nt][2], sc[nt][3]));
            }
            mx0 = fmaxf(mx0, __shfl_xor_sync(0xffffffffu, mx0, 1));
            mx0 = fmaxf(mx0, __shfl_xor_sync(0xffffffffu, mx0, 2));
            mx1 = fmaxf(mx1, __shfl_xor_sync(0xffffffffu, mx1, 1));
            mx1 = fmaxf(mx1, __shfl_xor_sync(0xffffffffu, mx1, 2));

            float nm0 = fmaxf(mrow[mt][0], mx0);
            float nm1 = fmaxf(mrow[mt][1], mx1);
            float corr0 = __expf(mrow[mt][0] - nm0);
            float corr1 = __expf(mrow[mt][1] - nm1);
            mrow[mt][0] = nm0;
            mrow[mt][1] = nm1;

            float sum0 = 0.f, sum1 = 0.f;
            #pragma unroll
            for (int nt = 0; nt < 8; ++nt) {
                sc[nt][0] = __expf(sc[nt][0] - nm0);
                sc[nt][1] = __expf(sc[nt][1] - nm0);
                sc[nt][2] = __expf(sc[nt][2] - nm1);
                sc[nt][3] = __expf(sc[nt][3] - nm1);
                sum0 += sc[nt][0] + sc[nt][1];
                sum1 += sc[nt][2] + sc[nt][3];
            }
            sum0 += __shfl_xor_sync(0xffffffffu, sum0, 1);
            sum0 += __shfl_xor_sync(0xffffffffu, sum0, 2);
            sum1 += __shfl_xor_sync(0xffffffffu, sum1, 1);
            sum1 += __shfl_xor_sync(0xffffffffu, sum1, 2);
            lrow[mt][0] = lrow[mt][0] * corr0 + sum0;
            lrow[mt][1] = lrow[mt][1] * corr1 + sum1;

            #pragma unroll
            for (int nt = 0; nt < 8; ++nt) {
                o[mt][nt][0] *= corr0;
                o[mt][nt][1] *= corr0;
                o[mt][nt][2] *= corr1;
                o[mt][nt][3] *= corr1;
            }

            // ---- O += P V (fp16, 2 products: ph*vh + ph*vl); skip zero tiles
            #pragma unroll
            for (int kv = 0; kv < 4; ++kv) {
                if (kv < npMax) {
                    uint32_t ph[4];
                    #pragma unroll
                    for (int half = 0; half < 2; ++half) {
                        const float* f = sc[2 * kv + half];
                        ph[2 * half]     = packhf(f[0], f[1]);
                        ph[2 * half + 1] = packhf(f[2], f[3]);
                    }
                    #pragma unroll
                    for (int np = 0; np < 4; ++np) {
                        uint32_t voff = (uint32_t)((s0 + kv * 16 + vRow) * AST + np * 16 + vCol);
                        uint32_t vh[4], vl[4];
                        ldsm4t(vh, sb + (V_HI + voff) * 2);
                        ldsm4t(vl, sb + (V_LO + voff) * 2);
                        mma16816h(o[mt][2 * np],     ph, vh[0], vh[1]);
                        mma16816h(o[mt][2 * np],     ph, vl[0], vl[1]);
                        mma16816h(o[mt][2 * np + 1], ph, vh[2], vh[3]);
                        mma16816h(o[mt][2 * np + 1], ph, vl[2], vl[3]);
                    }
                }
            }
        }
    }

    // ---- write out
    #pragma unroll
    for (int mt = 0; mt < 2; ++mt) {
        const int r0 = Rb[mt] + t4;
        const float inv0 = 1.f / lrow[mt][0];
        const float inv1 = 1.f / lrow[mt][1];
        #pragma unroll
        for (int nt = 0; nt < 8; ++nt) {
            int col = 8 * nt + 2 * tg;
            size_t o0 = ((size_t)b * TT + r0) * HH + col;
            *(float2*)(out + o0)           = make_float2(o[mt][nt][0] * inv0,
                                                         o[mt][nt][1] * inv0);
            *(float2*)(out + o0 + 8 * HH)  = make_float2(o[mt][nt][2] * inv1,
                                                         o[mt][nt][3] * inv1);
        }
    }
}

// ---------------------------------------------------------------------------
extern "C" void kernel_launch(void* const* d_in, const int* in_sizes, int n_in,
                              void* d_out, int out_size)
{
    const float* x  = (const float*)d_in[0];
    const float* Wq = (const float*)d_in[1];
    const float* Wk = (const float*)d_in[2];
    const float* Wv = (const float*)d_in[3];
    float* out = (float*)d_out;

    cudaFuncSetAttribute(proj_mma_kernel,
                         cudaFuncAttributeMaxDynamicSharedMemorySize, PROJ_SMEM);
    cudaFuncSetAttribute(attn_mma_kernel,
                         cudaFuncAttributeMaxDynamicSharedMemorySize, ATTN_SMEM);

    wsplit_kernel<<<36, 256>>>(Wq, Wk, Wv);
    proj_mma_kernel<<<MTOT / 64, 256, PROJ_SMEM>>>(x);
    attn_mma_kernel<<<BB, 256, ATTN_SMEM>>>(out);
}

// round 9
// speedup vs baseline: 3.1959x; 1.1106x over previous
#include <cuda_runtime.h>
#include <cuda_fp16.h>
#include <math.h>
#include <stdint.h>

#define BB   256
#define TT   256
#define DD   384
#define HH   64
#define MTOT (BB*TT)                       // 65536 rows
#define HEADELEMS ((size_t)MTOT*HH)

// scratch: q,k,v split fp16 hi/lo (attn operands) + split weights (fp16, proj)
__device__ __half g_h[3 * (size_t)MTOT * HH];
__device__ __half g_l[3 * (size_t)MTOT * HH];
__device__ __half g_wh[192 * 384];
__device__ __half g_wl[192 * 384];

// ---------------------------------------------------------------------------
__device__ __forceinline__ uint32_t smem_u32(const void* p) {
    uint32_t a;
    asm("{ .reg .u64 t; cvta.to.shared.u64 t, %1; cvt.u32.u64 %0, t; }"
        : "=r"(a) : "l"(p));
    return a;
}

__device__ __forceinline__ void ldsm4(uint32_t r[4], uint32_t addr) {
    asm volatile("ldmatrix.sync.aligned.m8n8.x4.shared.b16 {%0,%1,%2,%3}, [%4];"
                 : "=r"(r[0]), "=r"(r[1]), "=r"(r[2]), "=r"(r[3]) : "r"(addr));
}

__device__ __forceinline__ void ldsm4t(uint32_t r[4], uint32_t addr) {
    asm volatile("ldmatrix.sync.aligned.m8n8.x4.trans.shared.b16 {%0,%1,%2,%3}, [%4];"
                 : "=r"(r[0]), "=r"(r[1]), "=r"(r[2]), "=r"(r[3]) : "r"(addr));
}

// fp16 mma
__device__ __forceinline__ void mma16816h(float c[4], const uint32_t a[4],
                                          uint32_t b0, uint32_t b1) {
    asm volatile(
        "mma.sync.aligned.m16n8k16.row.col.f32.f16.f16.f32 "
        "{%0,%1,%2,%3}, {%4,%5,%6,%7}, {%8,%9}, {%0,%1,%2,%3};"
        : "+f"(c[0]), "+f"(c[1]), "+f"(c[2]), "+f"(c[3])
        : "r"(a[0]), "r"(a[1]), "r"(a[2]), "r"(a[3]), "r"(b0), "r"(b1));
}

// pack two f32 -> f16x2 (first arg in low half)
__device__ __forceinline__ uint32_t packhf(float lo, float hi) {
    __half2 h = __floats2half2_rn(lo, hi);
    return *(uint32_t*)&h;
}

__device__ __forceinline__ void cpasync16(uint32_t dst, const void* src) {
    asm volatile("cp.async.cg.shared.global [%0], [%1], 16;"
                 :: "r"(dst), "l"(src));
}

// ---------------------------------------------------------------------------
// Weight split prep: smem-tiled transpose, fp16 hi/lo.
// ---------------------------------------------------------------------------
__global__ void wsplit_kernel(const float* __restrict__ Wq,
                              const float* __restrict__ Wk,
                              const float* __restrict__ Wv) {
    __shared__ float ws[32][65];
    const int sel = blockIdx.x / 12;
    const int k0  = (blockIdx.x % 12) * 32;
    const float* W = (sel == 0) ? Wq : (sel == 1) ? Wk : Wv;
    const int tid = threadIdx.x;

    #pragma unroll
    for (int it = 0; it < 8; ++it) {
        int idx = tid + it * 256;          // 0..2047
        int k = idx >> 6, n = idx & 63;
        ws[k][n] = W[(size_t)(k0 + k) * HH + n];
    }
    __syncthreads();
    #pragma unroll
    for (int it = 0; it < 8; ++it) {
        int idx = tid + it * 256;
        int n = idx >> 5, k = idx & 31;
        float v = ws[k][n];
        __half h = __float2half_rn(v);
        size_t o = (size_t)(sel * 64 + n) * DD + k0 + k;
        g_wh[o] = h;
        g_wl[o] = __float2half_rn(v - __half2float(h));
    }
}

// ---------------------------------------------------------------------------
// Pipelined fp16 2-product projection: D = xh*wh + xh*wl.
// A: fp32 x -> LDG -> single fp16 -> STS, stride 40 halves, double buf.
// B: cp.async fp16 hi/lo from g_wh/g_wl, stride 40 halves, double buf.
// ---------------------------------------------------------------------------
#define KC    32
#define KS    40
#define ABUFH 2560     // halves: 64*40, hi only
#define B_BASE 5120    // halves: 2 A bufs
#define BBUFH 7680     // halves: 192*40 per array
#define PROJ_SMEM ((5120 + 30720) * 2)   // 71680 bytes

__global__ void __launch_bounds__(256, 2) proj_mma_kernel(const float* __restrict__ x)
{
    extern __shared__ __half sm[];
    const uint32_t sb = smem_u32(sm);
    const int tid  = threadIdx.x;
    const int lane = tid & 31;
    const int wid  = tid >> 5;
    const int wm   = wid & 1;
    const int wn   = wid >> 1;
    const int m0   = blockIdx.x * 64;

    const int aRow = (lane & 7) + ((lane >> 3) & 1) * 8;
    const int aCol = ((lane >> 4) & 1) * 8;
    const int bN   = (lane & 7) + ((lane >> 4) & 1) * 8;
    const int bK   = ((lane >> 3) & 1) * 8;

    float c[2][6][4];
    #pragma unroll
    for (int mt = 0; mt < 2; ++mt)
        #pragma unroll
        for (int nt = 0; nt < 6; ++nt)
            #pragma unroll
            for (int j = 0; j < 4; ++j) c[mt][nt][j] = 0.f;

    float4 aCur[2], aNxt[2];

    // ---- prologue: B(0) cp.async -> buf0, A(0) -> regs
    {
        #pragma unroll
        for (int it = 0; it < 6; ++it) {
            int idx = tid + it * 256;              // 0..1535
            int sub = (idx < 768) ? idx : idx - 768;
            int n   = sub >> 2;
            int kg  = (sub & 3) * 8;
            const __half* src = ((idx < 768) ? g_wh : g_wl) + (size_t)n * DD + kg;
            uint32_t dst = sb + (uint32_t)(B_BASE + ((idx < 768) ? 0 : BBUFH) +
                                           n * KS + kg) * 2;
            cpasync16(dst, src);
        }
        asm volatile("cp.async.commit_group;" ::: "memory");
        #pragma unroll
        for (int it = 0; it < 2; ++it) {
            int idx = tid + it * 256;              // 0..511 float4s
            int r = idx >> 3, c4 = (idx & 7) * 4;
            aCur[it] = *(const float4*)(x + (size_t)(m0 + r) * DD + c4);
        }
    }

    int p = 0;
    #pragma unroll 1
    for (int ch = 0; ch < 12; ++ch) {
        // ---- STS A(ch) into bufA[p] (single fp16)
        #pragma unroll
        for (int it = 0; it < 2; ++it) {
            int idx = tid + it * 256;
            int r = idx >> 3, c4 = (idx & 7) * 4;
            float4 v = aCur[it];
            int off = p * ABUFH + r * KS + c4;
            *(uint2*)(sm + off) = make_uint2(packhf(v.x, v.y), packhf(v.z, v.w));
        }

        // ---- drain B(ch), barrier
        asm volatile("cp.async.wait_group 0;" ::: "memory");
        __syncthreads();

        // ---- issue B(ch+1) + LDG A(ch+1); overlaps the MMA phase below
        if (ch < 11) {
            const int k1 = (ch + 1) * KC;
            #pragma unroll
            for (int it = 0; it < 6; ++it) {
                int idx = tid + it * 256;
                int sub = (idx < 768) ? idx : idx - 768;
                int n   = sub >> 2;
                int kg  = (sub & 3) * 8;
                const __half* src = ((idx < 768) ? g_wh : g_wl) + (size_t)n * DD + k1 + kg;
                uint32_t dst = sb + (uint32_t)(B_BASE + (p ^ 1) * 15360 +
                                               ((idx < 768) ? 0 : BBUFH) +
                                               n * KS + kg) * 2;
                cpasync16(dst, src);
            }
            asm volatile("cp.async.commit_group;" ::: "memory");
            #pragma unroll
            for (int it = 0; it < 2; ++it) {
                int idx = tid + it * 256;
                int r = idx >> 3, c4 = (idx & 7) * 4;
                aNxt[it] = *(const float4*)(x + (size_t)(m0 + r) * DD + k1 + c4);
            }
        }

        // ---- MMA over buffers p: 2 products per tile
        const uint32_t aBase = (uint32_t)(p * ABUFH);
        const uint32_t bBase = (uint32_t)(B_BASE + p * 15360);
        #pragma unroll
        for (int ks = 0; ks < 2; ++ks) {
            const int kk = ks * 16;
            uint32_t ah[2][4];
            #pragma unroll
            for (int mt = 0; mt < 2; ++mt) {
                uint32_t off = (uint32_t)((wm * 32 + mt * 16 + aRow) * KS + kk + aCol);
                ldsm4(ah[mt], sb + (aBase + off) * 2);
            }
            #pragma unroll
            for (int np = 0; np < 3; ++np) {
                uint32_t boff = (uint32_t)((wn * 48 + np * 16 + bN) * KS + kk + bK);
                uint32_t bh[4], bl[4];
                ldsm4(bh, sb + (bBase + boff) * 2);
                ldsm4(bl, sb + (bBase + BBUFH + boff) * 2);
                #pragma unroll
                for (int mt = 0; mt < 2; ++mt)
                    #pragma unroll
                    for (int sub = 0; sub < 2; ++sub) {
                        float* cc = c[mt][sub + np * 2];
                        mma16816h(cc, ah[mt], bh[sub * 2], bh[sub * 2 + 1]);
                        mma16816h(cc, ah[mt], bl[sub * 2], bl[sub * 2 + 1]);
                    }
            }
        }

        aCur[0] = aNxt[0];
        aCur[1] = aNxt[1];
        p ^= 1;
    }

    // ---- epilogue: fp32 acc -> fp16 hi/lo to g_h/g_l (q pre-scaled by 0.125;
    //      q_lo never read by attn -> skip its store)
    const int t4 = lane >> 2;
    const int c2 = (lane & 3) * 2;
    #pragma unroll
    for (int mt = 0; mt < 2; ++mt)
        #pragma unroll
        for (int nt = 0; nt < 6; ++nt) {
            int col = wn * 48 + nt * 8 + c2;
            int sel = col >> 6;
            int hc  = col & 63;
            float s = (sel == 0) ? 0.125f : 1.0f;
            float v0 = c[mt][nt][0] * s, v1 = c[mt][nt][1] * s;
            float v2 = c[mt][nt][2] * s, v3 = c[mt][nt][3] * s;
            __half2 hp01 = __floats2half2_rn(v0, v1);
            __half2 hp23 = __floats2half2_rn(v2, v3);
            size_t base = (size_t)sel * HEADELEMS +
                          (size_t)(m0 + wm * 32 + mt * 16 + t4) * HH + hc;
            *(uint32_t*)(g_h + base)          = *(uint32_t*)&hp01;
            *(uint32_t*)(g_h + base + 8 * HH) = *(uint32_t*)&hp23;
            if (sel != 0) {
                uint32_t lp01 = packhf(v0 - __low2float(hp01), v1 - __high2float(hp01));
                uint32_t lp23 = packhf(v2 - __low2float(hp23), v3 - __high2float(hp23));
                *(uint32_t*)(g_l + base)          = lp01;
                *(uint32_t*)(g_l + base + 8 * HH) = lp23;
            }
        }
}

// ---------------------------------------------------------------------------
// Tensor-core flash attention, fp16 2-product GEMMs (unchanged from R8).
// ---------------------------------------------------------------------------
#define AST 72
#define Q_HI 0
#define K_HI (256*AST)
#define K_LO (2*256*AST)
#define V_HI (3*256*AST)
#define V_LO (4*256*AST)
#define ATTN_SMEM (5*256*AST*2)    // 184320 bytes

__global__ void __launch_bounds__(256, 1) attn_mma_kernel(float* __restrict__ out)
{
    extern __shared__ __half asmem[];
    const uint32_t sb = smem_u32(asmem);
    const int b    = blockIdx.x;
    const int tid  = threadIdx.x;
    const int lane = tid & 31;
    const int w    = tid >> 5;
    const int t4   = lane >> 2;
    const int tg   = lane & 3;

    // ---- cp.async load: 5 arrays of [256][64] fp16 -> stride-72 smem
    {
        const __half* srcs[5] = { g_h,
                                  g_h + HEADELEMS, g_l + HEADELEMS,
                                  g_h + 2 * HEADELEMS, g_l + 2 * HEADELEMS };
        #pragma unroll
        for (int it = 0; it < 40; ++it) {
            const int arr = it >> 3;               // 8 iterations per array
            int rem = (tid + it * 256) - arr * 2048;
            int r   = rem >> 3;
            int kg  = (rem & 7) * 8;
            const __half* src = srcs[arr] + ((size_t)b * TT + r) * HH + kg;
            uint32_t dst = sb + (uint32_t)(arr * 256 * AST + r * AST + kg) * 2;
            cpasync16(dst, src);
        }
    }
    asm volatile("cp.async.commit_group;\n\tcp.async.wait_group 0;" ::: "memory");
    __syncthreads();

    const int Rb[2] = { 16 * w, 240 - 16 * w };

    float o[2][8][4];
    float mrow[2][2], lrow[2][2];
    #pragma unroll
    for (int mt = 0; mt < 2; ++mt) {
        mrow[mt][0] = mrow[mt][1] = -1e30f;
        lrow[mt][0] = lrow[mt][1] = 0.f;
        #pragma unroll
        for (int nt = 0; nt < 8; ++nt)
            #pragma unroll
            for (int j = 0; j < 4; ++j) o[mt][nt][j] = 0.f;
    }

    const int qRow = lane & 15;
    const int qCol = ((lane >> 4) & 1) * 8;
    const int kRow = (lane & 7) + ((lane >> 4) & 1) * 8;
    const int kCol = ((lane >> 3) & 1) * 8;
    const int vRow = lane & 15;
    const int vCol = ((lane >> 4) & 1) * 8;

    #pragma unroll 1
    for (int s0 = 0; s0 < TT; s0 += 64) {
        #pragma unroll
        for (int mt = 0; mt < 2; ++mt) {
            const int base = Rb[mt];
            if (s0 > base + 15) continue;

            const int npMax = min(4, ((base + 15 - s0) >> 4) + 1);

            // ---- S = Q K^T (fp16, 2 products: qh*kh + qh*kl)
            float sc[8][4];
            #pragma unroll
            for (int nt = 0; nt < 8; ++nt)
                #pragma unroll
                for (int j = 0; j < 4; ++j) sc[nt][j] = 0.f;

            #pragma unroll
            for (int kc = 0; kc < 4; ++kc) {
                uint32_t qh[4];
                uint32_t qoff = (uint32_t)((base + qRow) * AST + kc * 16 + qCol);
                ldsm4(qh, sb + (Q_HI + qoff) * 2);
                #pragma unroll
                for (int np = 0; np < 4; ++np) {
                    if (np < npMax) {
                        uint32_t koff = (uint32_t)((s0 + np * 16 + kRow) * AST + kc * 16 + kCol);
                        uint32_t kh[4], kl[4];
                        ldsm4(kh, sb + (K_HI + koff) * 2);
                        ldsm4(kl, sb + (K_LO + koff) * 2);
                        mma16816h(sc[2 * np],     qh, kh[0], kh[1]);
                        mma16816h(sc[2 * np],     qh, kl[0], kl[1]);
                        mma16816h(sc[2 * np + 1], qh, kh[2], kh[3]);
                        mma16816h(sc[2 * np + 1], qh, kl[2], kl[3]);
                    }
                }
            }

            // ---- causal mask + online softmax
            const int r0 = base + t4;
            const int r1 = r0 + 8;
            #pragma unroll
            for (int nt = 0; nt < 8; ++nt) {
                int col = s0 + 8 * nt + 2 * tg;
                if (col     > r0) sc[nt][0] = -1e30f;
                if (col + 1 > r0) sc[nt][1] = -1e30f;
                if (col     > r1) sc[nt][2] = -1e30f;
                if (col + 1 > r1) sc[nt][3] = -1e30f;
            }
            float mx0 = sc[0][0], mx1 = sc[0][2];
            #pragma unroll
            for (int nt = 0; nt < 8; ++nt) {
                mx0 = fmaxf(mx0, fmaxf(sc[nt][0], sc[nt][1]));
                mx1 = fmaxf(mx1, fmaxf(sc[nt][2], sc[nt][3]));
            }
            mx0 = fmaxf(mx0, __shfl_xor_sync(0xffffffffu, mx0, 1));
            mx0 = fmaxf(mx0, __shfl_xor_sync(0xffffffffu, mx0, 2));
            mx1 = fmaxf(mx1, __shfl_xor_sync(0xffffffffu, mx1, 1));
            mx1 = fmaxf(mx1, __shfl_xor_sync(0xffffffffu, mx1, 2));

            float nm0 = fmaxf(mrow[mt][0], mx0);
            float nm1 = fmaxf(mrow[mt][1], mx1);
            float corr0 = __expf(mrow[mt][0] - nm0);
            float corr1 = __expf(mrow[mt][1] - nm1);
            mrow[mt][0] = nm0;
            mrow[mt][1] = nm1;

            float sum0 = 0.f, sum1 = 0.f;
            #pragma unroll
            for (int nt = 0; nt < 8; ++nt) {
                sc[nt][0] = __expf(sc[nt][0] - nm0);
                sc[nt][1] = __expf(sc[nt][1] - nm0);
                sc[nt][2] = __expf(sc[nt][2] - nm1);
                sc[nt][3] = __expf(sc[nt][3] - nm1);
                sum0 += sc[nt][0] + sc[nt][1];
                sum1 += sc[nt][2] + sc[nt][3];
            }
            sum0 += __shfl_xor_sync(0xffffffffu, sum0, 1);
            sum0 += __shfl_xor_sync(0xffffffffu, sum0, 2);
            sum1 += __shfl_xor_sync(0xffffffffu, sum1, 1);
            sum1 += __shfl_xor_sync(0xffffffffu, sum1, 2);
            lrow[mt][0] = lrow[mt][0] * corr0 + sum0;
            lrow[mt][1] = lrow[mt][1] * corr1 + sum1;

            #pragma unroll
            for (int nt = 0; nt < 8; ++nt) {
                o[mt][nt][0] *= corr0;
                o[mt][nt][1] *= corr0;
                o[mt][nt][2] *= corr1;
                o[mt][nt][3] *= corr1;
            }

            // ---- O += P V (fp16, 2 products: ph*vh + ph*vl); skip zero tiles
            #pragma unroll
            for (int kv = 0; kv < 4; ++kv) {
                if (kv < npMax) {
                    uint32_t ph[4];
                    #pragma unroll
                    for (int half = 0; half < 2; ++half) {
                        const float* f = sc[2 * kv + half];
                        ph[2 * half]     = packhf(f[0], f[1]);
                        ph[2 * half + 1] = packhf(f[2], f[3]);
                    }
                    #pragma unroll
                    for (int np = 0; np < 4; ++np) {
                        uint32_t voff = (uint32_t)((s0 + kv * 16 + vRow) * AST + np * 16 + vCol);
                        uint32_t vh[4], vl[4];
                        ldsm4t(vh, sb + (V_HI + voff) * 2);
                        ldsm4t(vl, sb + (V_LO + voff) * 2);
                        mma16816h(o[mt][2 * np],     ph, vh[0], vh[1]);
                        mma16816h(o[mt][2 * np],     ph, vl[0], vl[1]);
                        mma16816h(o[mt][2 * np + 1], ph, vh[2], vh[3]);
                        mma16816h(o[mt][2 * np + 1], ph, vl[2], vl[3]);
                    }
                }
            }
        }
    }

    // ---- write out
    #pragma unroll
    for (int mt = 0; mt < 2; ++mt) {
        const int r0 = Rb[mt] + t4;
        const float inv0 = 1.f / lrow[mt][0];
        const float inv1 = 1.f / lrow[mt][1];
        #pragma unroll
        for (int nt = 0; nt < 8; ++nt) {
            int col = 8 * nt + 2 * tg;
            size_t o0 = ((size_t)b * TT + r0) * HH + col;
            *(float2*)(out + o0)           = make_float2(o[mt][nt][0] * inv0,
                                                         o[mt][nt][1] * inv0);
            *(float2*)(out + o0 + 8 * HH)  = make_float2(o[mt][nt][2] * inv1,
                                                         o[mt][nt][3] * inv1);
        }
    }
}

// ---------------------------------------------------------------------------
extern "C" void kernel_launch(void* const* d_in, const int* in_sizes, int n_in,
                              void* d_out, int out_size)
{
    const float* x  = (const float*)d_in[0];
    const float* Wq = (const float*)d_in[1];
    const float* Wk = (const float*)d_in[2];
    const float* Wv = (const float*)d_in[3];
    float* out = (float*)d_out;

    cudaFuncSetAttribute(proj_mma_kernel,
                         cudaFuncAttributeMaxDynamicSharedMemorySize, PROJ_SMEM);
    cudaFuncSetAttribute(attn_mma_kernel,
                         cudaFuncAttributeMaxDynamicSharedMemorySize, ATTN_SMEM);

    wsplit_kernel<<<36, 256>>>(Wq, Wk, Wv);
    proj_mma_kernel<<<MTOT / 64, 256, PROJ_SMEM>>>(x);
    attn_mma_kernel<<<BB, 256, ATTN_SMEM>>>(out);
}

// round 10
// speedup vs baseline: 3.6073x; 1.1287x over previous
#include <cuda_runtime.h>
#include <cuda_fp16.h>
#include <math.h>
#include <stdint.h>

#define BB   256
#define TT   256
#define DD   384
#define HH   64
#define MTOT (BB*TT)                       // 65536 rows
#define HEADELEMS ((size_t)MTOT*HH)

// scratch: q,k,v fp16 (attn operands) + split weights (fp16 hi/lo, proj)
__device__ __half g_h[3 * (size_t)MTOT * HH];
__device__ __half g_wh[192 * 384];
__device__ __half g_wl[192 * 384];

// ---------------------------------------------------------------------------
__device__ __forceinline__ uint32_t smem_u32(const void* p) {
    uint32_t a;
    asm("{ .reg .u64 t; cvta.to.shared.u64 t, %1; cvt.u32.u64 %0, t; }"
        : "=r"(a) : "l"(p));
    return a;
}

__device__ __forceinline__ void ldsm4(uint32_t r[4], uint32_t addr) {
    asm volatile("ldmatrix.sync.aligned.m8n8.x4.shared.b16 {%0,%1,%2,%3}, [%4];"
                 : "=r"(r[0]), "=r"(r[1]), "=r"(r[2]), "=r"(r[3]) : "r"(addr));
}

__device__ __forceinline__ void ldsm4t(uint32_t r[4], uint32_t addr) {
    asm volatile("ldmatrix.sync.aligned.m8n8.x4.trans.shared.b16 {%0,%1,%2,%3}, [%4];"
                 : "=r"(r[0]), "=r"(r[1]), "=r"(r[2]), "=r"(r[3]) : "r"(addr));
}

// fp16 mma
__device__ __forceinline__ void mma16816h(float c[4], const uint32_t a[4],
                                          uint32_t b0, uint32_t b1) {
    asm volatile(
        "mma.sync.aligned.m16n8k16.row.col.f32.f16.f16.f32 "
        "{%0,%1,%2,%3}, {%4,%5,%6,%7}, {%8,%9}, {%0,%1,%2,%3};"
        : "+f"(c[0]), "+f"(c[1]), "+f"(c[2]), "+f"(c[3])
        : "r"(a[0]), "r"(a[1]), "r"(a[2]), "r"(a[3]), "r"(b0), "r"(b1));
}

// pack two f32 -> f16x2 (first arg in low half)
__device__ __forceinline__ uint32_t packhf(float lo, float hi) {
    __half2 h = __floats2half2_rn(lo, hi);
    return *(uint32_t*)&h;
}

__device__ __forceinline__ void cpasync16(uint32_t dst, const void* src) {
    asm volatile("cp.async.cg.shared.global [%0], [%1], 16;"
                 :: "r"(dst), "l"(src));
}

// ---------------------------------------------------------------------------
// Weight split prep: smem-tiled transpose, fp16 hi/lo.
// ---------------------------------------------------------------------------
__global__ void wsplit_kernel(const float* __restrict__ Wq,
                              const float* __restrict__ Wk,
                              const float* __restrict__ Wv) {
    __shared__ float ws[32][65];
    const int sel = blockIdx.x / 12;
    const int k0  = (blockIdx.x % 12) * 32;
    const float* W = (sel == 0) ? Wq : (sel == 1) ? Wk : Wv;
    const int tid = threadIdx.x;

    #pragma unroll
    for (int it = 0; it < 8; ++it) {
        int idx = tid + it * 256;          // 0..2047
        int k = idx >> 6, n = idx & 63;
        ws[k][n] = W[(size_t)(k0 + k) * HH + n];
    }
    __syncthreads();
    #pragma unroll
    for (int it = 0; it < 8; ++it) {
        int idx = tid + it * 256;
        int n = idx >> 5, k = idx & 31;
        float v = ws[k][n];
        __half h = __float2half_rn(v);
        size_t o = (size_t)(sel * 64 + n) * DD + k0 + k;
        g_wh[o] = h;
        g_wl[o] = __float2half_rn(v - __half2float(h));
    }
}

// ---------------------------------------------------------------------------
// Pipelined fp16 2-product projection: D = xh*wh + xh*wl.
// ---------------------------------------------------------------------------
#define KC    32
#define KS    40
#define ABUFH 2560     // halves: 64*40, hi only
#define B_BASE 5120    // halves: 2 A bufs
#define BBUFH 7680     // halves: 192*40 per array
#define PROJ_SMEM ((5120 + 30720) * 2)   // 71680 bytes

__global__ void __launch_bounds__(256, 2) proj_mma_kernel(const float* __restrict__ x)
{
    extern __shared__ __half sm[];
    const uint32_t sb = smem_u32(sm);
    const int tid  = threadIdx.x;
    const int lane = tid & 31;
    const int wid  = tid >> 5;
    const int wm   = wid & 1;
    const int wn   = wid >> 1;
    const int m0   = blockIdx.x * 64;

    const int aRow = (lane & 7) + ((lane >> 3) & 1) * 8;
    const int aCol = ((lane >> 4) & 1) * 8;
    const int bN   = (lane & 7) + ((lane >> 4) & 1) * 8;
    const int bK   = ((lane >> 3) & 1) * 8;

    float c[2][6][4];
    #pragma unroll
    for (int mt = 0; mt < 2; ++mt)
        #pragma unroll
        for (int nt = 0; nt < 6; ++nt)
            #pragma unroll
            for (int j = 0; j < 4; ++j) c[mt][nt][j] = 0.f;

    float4 aCur[2], aNxt[2];

    // ---- prologue: B(0) cp.async -> buf0, A(0) -> regs
    {
        #pragma unroll
        for (int it = 0; it < 6; ++it) {
            int idx = tid + it * 256;              // 0..1535
            int sub = (idx < 768) ? idx : idx - 768;
            int n   = sub >> 2;
            int kg  = (sub & 3) * 8;
            const __half* src = ((idx < 768) ? g_wh : g_wl) + (size_t)n * DD + kg;
            uint32_t dst = sb + (uint32_t)(B_BASE + ((idx < 768) ? 0 : BBUFH) +
                                           n * KS + kg) * 2;
            cpasync16(dst, src);
        }
        asm volatile("cp.async.commit_group;" ::: "memory");
        #pragma unroll
        for (int it = 0; it < 2; ++it) {
            int idx = tid + it * 256;              // 0..511 float4s
            int r = idx >> 3, c4 = (idx & 7) * 4;
            aCur[it] = *(const float4*)(x + (size_t)(m0 + r) * DD + c4);
        }
    }

    int p = 0;
    #pragma unroll 1
    for (int ch = 0; ch < 12; ++ch) {
        // ---- STS A(ch) into bufA[p] (single fp16)
        #pragma unroll
        for (int it = 0; it < 2; ++it) {
            int idx = tid + it * 256;
            int r = idx >> 3, c4 = (idx & 7) * 4;
            float4 v = aCur[it];
            int off = p * ABUFH + r * KS + c4;
            *(uint2*)(sm + off) = make_uint2(packhf(v.x, v.y), packhf(v.z, v.w));
        }

        // ---- drain B(ch), barrier
        asm volatile("cp.async.wait_group 0;" ::: "memory");
        __syncthreads();

        // ---- issue B(ch+1) + LDG A(ch+1); overlaps the MMA phase below
        if (ch < 11) {
            const int k1 = (ch + 1) * KC;
            #pragma unroll
            for (int it = 0; it < 6; ++it) {
                int idx = tid + it * 256;
                int sub = (idx < 768) ? idx : idx - 768;
                int n   = sub >> 2;
                int kg  = (sub & 3) * 8;
                const __half* src = ((idx < 768) ? g_wh : g_wl) + (size_t)n * DD + k1 + kg;
                uint32_t dst = sb + (uint32_t)(B_BASE + (p ^ 1) * 15360 +
                                               ((idx < 768) ? 0 : BBUFH) +
                                               n * KS + kg) * 2;
                cpasync16(dst, src);
            }
            asm volatile("cp.async.commit_group;" ::: "memory");
            #pragma unroll
            for (int it = 0; it < 2; ++it) {
                int idx = tid + it * 256;
                int r = idx >> 3, c4 = (idx & 7) * 4;
                aNxt[it] = *(const float4*)(x + (size_t)(m0 + r) * DD + k1 + c4);
            }
        }

        // ---- MMA over buffers p: 2 products per tile
        const uint32_t aBase = (uint32_t)(p * ABUFH);
        const uint32_t bBase = (uint32_t)(B_BASE + p * 15360);
        #pragma unroll
        for (int ks = 0; ks < 2; ++ks) {
            const int kk = ks * 16;
            uint32_t ah[2][4];
            #pragma unroll
            for (int mt = 0; mt < 2; ++mt) {
                uint32_t off = (uint32_t)((wm * 32 + mt * 16 + aRow) * KS + kk + aCol);
                ldsm4(ah[mt], sb + (aBase + off) * 2);
            }
            #pragma unroll
            for (int np = 0; np < 3; ++np) {
                uint32_t boff = (uint32_t)((wn * 48 + np * 16 + bN) * KS + kk + bK);
                uint32_t bh[4], bl[4];
                ldsm4(bh, sb + (bBase + boff) * 2);
                ldsm4(bl, sb + (bBase + BBUFH + boff) * 2);
                #pragma unroll
                for (int mt = 0; mt < 2; ++mt)
                    #pragma unroll
                    for (int sub = 0; sub < 2; ++sub) {
                        float* cc = c[mt][sub + np * 2];
                        mma16816h(cc, ah[mt], bh[sub * 2], bh[sub * 2 + 1]);
                        mma16816h(cc, ah[mt], bl[sub * 2], bl[sub * 2 + 1]);
                    }
            }
        }

        aCur[0] = aNxt[0];
        aCur[1] = aNxt[1];
        p ^= 1;
    }

    // ---- epilogue: fp32 acc -> single fp16 to g_h (q pre-scaled by 0.125)
    const int t4 = lane >> 2;
    const int c2 = (lane & 3) * 2;
    #pragma unroll
    for (int mt = 0; mt < 2; ++mt)
        #pragma unroll
        for (int nt = 0; nt < 6; ++nt) {
            int col = wn * 48 + nt * 8 + c2;
            int sel = col >> 6;
            int hc  = col & 63;
            float s = (sel == 0) ? 0.125f : 1.0f;
            size_t base = (size_t)sel * HEADELEMS +
                          (size_t)(m0 + wm * 32 + mt * 16 + t4) * HH + hc;
            *(uint32_t*)(g_h + base) =
                packhf(c[mt][nt][0] * s, c[mt][nt][1] * s);
            *(uint32_t*)(g_h + base + 8 * HH) =
                packhf(c[mt][nt][2] * s, c[mt][nt][3] * s);
        }
}

// ---------------------------------------------------------------------------
// Tensor-core flash attention, fp16 single-product GEMMs, 2 CTAs/SM.
// smem: q, k, v (3 arrays, stride 72 halves) = 108 KB.
// ---------------------------------------------------------------------------
#define AST 72
#define Q_S 0
#define K_S (256*AST)
#define V_S (2*256*AST)
#define ATTN_SMEM (3*256*AST*2)    // 110592 bytes

__global__ void __launch_bounds__(256, 2) attn_mma_kernel(float* __restrict__ out)
{
    extern __shared__ __half asmem[];
    const uint32_t sb = smem_u32(asmem);
    const int b    = blockIdx.x;
    const int tid  = threadIdx.x;
    const int lane = tid & 31;
    const int w    = tid >> 5;
    const int t4   = lane >> 2;
    const int tg   = lane & 3;

    // ---- cp.async load: 3 arrays of [256][64] fp16 -> stride-72 smem
    #pragma unroll
    for (int it = 0; it < 24; ++it) {
        const int arr = it >> 3;               // 8 iterations per array
        int rem = (tid + it * 256) - arr * 2048;
        int r   = rem >> 3;
        int kg  = (rem & 7) * 8;
        const __half* src = g_h + (size_t)arr * HEADELEMS +
                            ((size_t)b * TT + r) * HH + kg;
        uint32_t dst = sb + (uint32_t)(arr * 256 * AST + r * AST + kg) * 2;
        cpasync16(dst, src);
    }
    asm volatile("cp.async.commit_group;\n\tcp.async.wait_group 0;" ::: "memory");
    __syncthreads();

    const int Rb[2] = { 16 * w, 240 - 16 * w };

    float o[2][8][4];
    float mrow[2][2], lrow[2][2];
    #pragma unroll
    for (int mt = 0; mt < 2; ++mt) {
        mrow[mt][0] = mrow[mt][1] = -1e30f;
        lrow[mt][0] = lrow[mt][1] = 0.f;
        #pragma unroll
        for (int nt = 0; nt < 8; ++nt)
            #pragma unroll
            for (int j = 0; j < 4; ++j) o[mt][nt][j] = 0.f;
    }

    const int qRow = lane & 15;
    const int qCol = ((lane >> 4) & 1) * 8;
    const int kRow = (lane & 7) + ((lane >> 4) & 1) * 8;
    const int kCol = ((lane >> 3) & 1) * 8;
    const int vRow = lane & 15;
    const int vCol = ((lane >> 4) & 1) * 8;

    #pragma unroll 1
    for (int s0 = 0; s0 < TT; s0 += 64) {
        #pragma unroll
        for (int mt = 0; mt < 2; ++mt) {
            const int base = Rb[mt];
            if (s0 > base + 15) continue;

            const int npMax = min(4, ((base + 15 - s0) >> 4) + 1);

            // ---- S = Q K^T (fp16, single product)
            float sc[8][4];
            #pragma unroll
            for (int nt = 0; nt < 8; ++nt)
                #pragma unroll
                for (int j = 0; j < 4; ++j) sc[nt][j] = 0.f;

            #pragma unroll
            for (int kc = 0; kc < 4; ++kc) {
                uint32_t qh[4];
                uint32_t qoff = (uint32_t)((base + qRow) * AST + kc * 16 + qCol);
                ldsm4(qh, sb + (Q_S + qoff) * 2);
                #pragma unroll
                for (int np = 0; np < 4; ++np) {
                    if (np < npMax) {
                        uint32_t koff = (uint32_t)((s0 + np * 16 + kRow) * AST + kc * 16 + kCol);
                        uint32_t kh[4];
                        ldsm4(kh, sb + (K_S + koff) * 2);
                        mma16816h(sc[2 * np],     qh, kh[0], kh[1]);
                        mma16816h(sc[2 * np + 1], qh, kh[2], kh[3]);
                    }
                }
            }

            // ---- causal mask + online softmax
            const int r0 = base + t4;
            const int r1 = r0 + 8;
            #pragma unroll
            for (int nt = 0; nt < 8; ++nt) {
                int col = s0 + 8 * nt + 2 * tg;
                if (col     > r0) sc[nt][0] = -1e30f;
                if (col + 1 > r0) sc[nt][1] = -1e30f;
                if (col     > r1) sc[nt][2] = -1e30f;
                if (col + 1 > r1) sc[nt][3] = -1e30f;
            }
            float mx0 = sc[0][0], mx1 = sc[0][2];
            #pragma unroll
            for (int nt = 0; nt < 8; ++nt) {
                mx0 = fmaxf(mx0, fmaxf(sc[nt][0], sc[nt][1]));
                mx1 = fmaxf(mx1, fmaxf(sc[nt][2], sc[nt][3]));
            }
            mx0 = fmaxf(mx0, __shfl_xor_sync(0xffffffffu, mx0, 1));
            mx0 = fmaxf(mx0, __shfl_xor_sync(0xffffffffu, mx0, 2));
            mx1 = fmaxf(mx1, __shfl_xor_sync(0xffffffffu, mx1, 1));
            mx1 = fmaxf(mx1, __shfl_xor_sync(0xffffffffu, mx1, 2));

            float nm0 = fmaxf(mrow[mt][0], mx0);
            float nm1 = fmaxf(mrow[mt][1], mx1);
            float corr0 = __expf(mrow[mt][0] - nm0);
            float corr1 = __expf(mrow[mt][1] - nm1);
            mrow[mt][0] = nm0;
            mrow[mt][1] = nm1;

            float sum0 = 0.f, sum1 = 0.f;
            #pragma unroll
            for (int nt = 0; nt < 8; ++nt) {
                sc[nt][0] = __expf(sc[nt][0] - nm0);
                sc[nt][1] = __expf(sc[nt][1] - nm0);
                sc[nt][2] = __expf(sc[nt][2] - nm1);
                sc[nt][3] = __expf(sc[nt][3] - nm1);
                sum0 += sc[nt][0] + sc[nt][1];
                sum1 += sc[nt][2] + sc[nt][3];
            }
            sum0 += __shfl_xor_sync(0xffffffffu, sum0, 1);
            sum0 += __shfl_xor_sync(0xffffffffu, sum0, 2);
            sum1 += __shfl_xor_sync(0xffffffffu, sum1, 1);
            sum1 += __shfl_xor_sync(0xffffffffu, sum1, 2);
            lrow[mt][0] = lrow[mt][0] * corr0 + sum0;
            lrow[mt][1] = lrow[mt][1] * corr1 + sum1;

            #pragma unroll
            for (int nt = 0; nt < 8; ++nt) {
                o[mt][nt][0] *= corr0;
                o[mt][nt][1] *= corr0;
                o[mt][nt][2] *= corr1;
                o[mt][nt][3] *= corr1;
            }

            // ---- O += P V (fp16, single product); skip zero tiles
            #pragma unroll
            for (int kv = 0; kv < 4; ++kv) {
                if (kv < npMax) {
                    uint32_t ph[4];
                    #pragma unroll
                    for (int half = 0; half < 2; ++half) {
                        const float* f = sc[2 * kv + half];
                        ph[2 * half]     = packhf(f[0], f[1]);
                        ph[2 * half + 1] = packhf(f[2], f[3]);
                    }
                    #pragma unroll
                    for (int np = 0; np < 4; ++np) {
                        uint32_t voff = (uint32_t)((s0 + kv * 16 + vRow) * AST + np * 16 + vCol);
                        uint32_t vh[4];
                        ldsm4t(vh, sb + (V_S + voff) * 2);
                        mma16816h(o[mt][2 * np],     ph, vh[0], vh[1]);
                        mma16816h(o[mt][2 * np + 1], ph, vh[2], vh[3]);
                    }
                }
            }
        }
    }

    // ---- write out
    #pragma unroll
    for (int mt = 0; mt < 2; ++mt) {
        const int r0 = Rb[mt] + t4;
        const float inv0 = 1.f / lrow[mt][0];
        const float inv1 = 1.f / lrow[mt][1];
        #pragma unroll
        for (int nt = 0; nt < 8; ++nt) {
            int col = 8 * nt + 2 * tg;
            size_t o0 = ((size_t)b * TT + r0) * HH + col;
            *(float2*)(out + o0)           = make_float2(o[mt][nt][0] * inv0,
                                                         o[mt][nt][1] * inv0);
            *(float2*)(out + o0 + 8 * HH)  = make_float2(o[mt][nt][2] * inv1,
                                                         o[mt][nt][3] * inv1);
        }
    }
}

// ---------------------------------------------------------------------------
extern "C" void kernel_launch(void* const* d_in, const int* in_sizes, int n_in,
                              void* d_out, int out_size)
{
    const float* x  = (const float*)d_in[0];
    const float* Wq = (const float*)d_in[1];
    const float* Wk = (const float*)d_in[2];
    const float* Wv = (const float*)d_in[3];
    float* out = (float*)d_out;

    cudaFuncSetAttribute(proj_mma_kernel,
                         cudaFuncAttributeMaxDynamicSharedMemorySize, PROJ_SMEM);
    cudaFuncSetAttribute(attn_mma_kernel,
                         cudaFuncAttributeMaxDynamicSharedMemorySize, ATTN_SMEM);

    wsplit_kernel<<<36, 256>>>(Wq, Wk, Wv);
    proj_mma_kernel<<<MTOT / 64, 256, PROJ_SMEM>>>(x);
    attn_mma_kernel<<<BB, 256, ATTN_SMEM>>>(out);
}

// round 11
// speedup vs baseline: 4.2958x; 1.1909x over previous
#include <cuda_runtime.h>
#include <cuda_fp16.h>
#include <math.h>
#include <stdint.h>

#define BB   256
#define TT   256
#define DD   384
#define HH   64
#define MTOT (BB*TT)                       // 65536 rows
#define HEADELEMS ((size_t)MTOT*HH)

// scratch: q,k,v fp16 (attn operands) + transposed fp16 weights (proj)
__device__ __half g_h[3 * (size_t)MTOT * HH];
__device__ __half g_wh[192 * 384];

// ---------------------------------------------------------------------------
__device__ __forceinline__ uint32_t smem_u32(const void* p) {
    uint32_t a;
    asm("{ .reg .u64 t; cvta.to.shared.u64 t, %1; cvt.u32.u64 %0, t; }"
        : "=r"(a) : "l"(p));
    return a;
}

__device__ __forceinline__ void ldsm4(uint32_t r[4], uint32_t addr) {
    asm volatile("ldmatrix.sync.aligned.m8n8.x4.shared.b16 {%0,%1,%2,%3}, [%4];"
                 : "=r"(r[0]), "=r"(r[1]), "=r"(r[2]), "=r"(r[3]) : "r"(addr));
}

__device__ __forceinline__ void ldsm4t(uint32_t r[4], uint32_t addr) {
    asm volatile("ldmatrix.sync.aligned.m8n8.x4.trans.shared.b16 {%0,%1,%2,%3}, [%4];"
                 : "=r"(r[0]), "=r"(r[1]), "=r"(r[2]), "=r"(r[3]) : "r"(addr));
}

// fp16 mma
__device__ __forceinline__ void mma16816h(float c[4], const uint32_t a[4],
                                          uint32_t b0, uint32_t b1) {
    asm volatile(
        "mma.sync.aligned.m16n8k16.row.col.f32.f16.f16.f32 "
        "{%0,%1,%2,%3}, {%4,%5,%6,%7}, {%8,%9}, {%0,%1,%2,%3};"
        : "+f"(c[0]), "+f"(c[1]), "+f"(c[2]), "+f"(c[3])
        : "r"(a[0]), "r"(a[1]), "r"(a[2]), "r"(a[3]), "r"(b0), "r"(b1));
}

// pack two f32 -> f16x2 (first arg in low half)
__device__ __forceinline__ uint32_t packhf(float lo, float hi) {
    __half2 h = __floats2half2_rn(lo, hi);
    return *(uint32_t*)&h;
}

__device__ __forceinline__ void cpasync16(uint32_t dst, const void* src) {
    asm volatile("cp.async.cg.shared.global [%0], [%1], 16;"
                 :: "r"(dst), "l"(src));
}

// ---------------------------------------------------------------------------
// Weight prep: smem-tiled transpose, single fp16.
// ---------------------------------------------------------------------------
__global__ void wsplit_kernel(const float* __restrict__ Wq,
                              const float* __restrict__ Wk,
                              const float* __restrict__ Wv) {
    __shared__ float ws[32][65];
    const int sel = blockIdx.x / 12;
    const int k0  = (blockIdx.x % 12) * 32;
    const float* W = (sel == 0) ? Wq : (sel == 1) ? Wk : Wv;
    const int tid = threadIdx.x;

    #pragma unroll
    for (int it = 0; it < 8; ++it) {
        int idx = tid + it * 256;          // 0..2047
        int k = idx >> 6, n = idx & 63;
        ws[k][n] = W[(size_t)(k0 + k) * HH + n];
    }
    __syncthreads();
    #pragma unroll
    for (int it = 0; it < 8; ++it) {
        int idx = tid + it * 256;
        int n = idx >> 5, k = idx & 31;
        g_wh[(size_t)(sel * 64 + n) * DD + k0 + k] = __float2half_rn(ws[k][n]);
    }
}

// ---------------------------------------------------------------------------
// Pipelined fp16 single-product projection: D = xh*wh.
// A: fp32 x -> LDG -> fp16 -> STS, stride 40 halves, double buf.
// B: cp.async fp16 from g_wh, stride 40 halves, double buf.
// ---------------------------------------------------------------------------
#define KC    32
#define KS    40
#define ABUFH 2560     // halves: 64*40
#define B_BASE 5120    // halves: 2 A bufs
#define BBUFH 7680     // halves: 192*40
#define PROJ_SMEM ((5120 + 15360) * 2)   // 40960 bytes

__global__ void __launch_bounds__(256, 2) proj_mma_kernel(const float* __restrict__ x)
{
    extern __shared__ __half sm[];
    const uint32_t sb = smem_u32(sm);
    const int tid  = threadIdx.x;
    const int lane = tid & 31;
    const int wid  = tid >> 5;
    const int wm   = wid & 1;
    const int wn   = wid >> 1;
    const int m0   = blockIdx.x * 64;

    const int aRow = (lane & 7) + ((lane >> 3) & 1) * 8;
    const int aCol = ((lane >> 4) & 1) * 8;
    const int bN   = (lane & 7) + ((lane >> 4) & 1) * 8;
    const int bK   = ((lane >> 3) & 1) * 8;

    float c[2][6][4];
    #pragma unroll
    for (int mt = 0; mt < 2; ++mt)
        #pragma unroll
        for (int nt = 0; nt < 6; ++nt)
            #pragma unroll
            for (int j = 0; j < 4; ++j) c[mt][nt][j] = 0.f;

    float4 aCur[2], aNxt[2];

    // ---- prologue: B(0) cp.async -> buf0, A(0) -> regs
    {
        #pragma unroll
        for (int it = 0; it < 3; ++it) {
            int idx = tid + it * 256;              // 0..767
            int n   = idx >> 2;
            int kg  = (idx & 3) * 8;
            cpasync16(sb + (uint32_t)(B_BASE + n * KS + kg) * 2,
                      g_wh + (size_t)n * DD + kg);
        }
        asm volatile("cp.async.commit_group;" ::: "memory");
        #pragma unroll
        for (int it = 0; it < 2; ++it) {
            int idx = tid + it * 256;              // 0..511 float4s
            int r = idx >> 3, c4 = (idx & 7) * 4;
            aCur[it] = *(const float4*)(x + (size_t)(m0 + r) * DD + c4);
        }
    }

    int p = 0;
    #pragma unroll 1
    for (int ch = 0; ch < 12; ++ch) {
        // ---- STS A(ch) into bufA[p] (single fp16)
        #pragma unroll
        for (int it = 0; it < 2; ++it) {
            int idx = tid + it * 256;
            int r = idx >> 3, c4 = (idx & 7) * 4;
            float4 v = aCur[it];
            int off = p * ABUFH + r * KS + c4;
            *(uint2*)(sm + off) = make_uint2(packhf(v.x, v.y), packhf(v.z, v.w));
        }

        // ---- drain B(ch), barrier
        asm volatile("cp.async.wait_group 0;" ::: "memory");
        __syncthreads();

        // ---- issue B(ch+1) + LDG A(ch+1); overlaps the MMA phase below
        if (ch < 11) {
            const int k1 = (ch + 1) * KC;
            #pragma unroll
            for (int it = 0; it < 3; ++it) {
                int idx = tid + it * 256;
                int n   = idx >> 2;
                int kg  = (idx & 3) * 8;
                cpasync16(sb + (uint32_t)(B_BASE + (p ^ 1) * BBUFH + n * KS + kg) * 2,
                          g_wh + (size_t)n * DD + k1 + kg);
            }
            asm volatile("cp.async.commit_group;" ::: "memory");
            #pragma unroll
            for (int it = 0; it < 2; ++it) {
                int idx = tid + it * 256;
                int r = idx >> 3, c4 = (idx & 7) * 4;
                aNxt[it] = *(const float4*)(x + (size_t)(m0 + r) * DD + k1 + c4);
            }
        }

        // ---- MMA over buffers p: single product per tile
        const uint32_t aBase = (uint32_t)(p * ABUFH);
        const uint32_t bBase = (uint32_t)(B_BASE + p * BBUFH);
        #pragma unroll
        for (int ks = 0; ks < 2; ++ks) {
            const int kk = ks * 16;
            uint32_t ah[2][4];
            #pragma unroll
            for (int mt = 0; mt < 2; ++mt) {
                uint32_t off = (uint32_t)((wm * 32 + mt * 16 + aRow) * KS + kk + aCol);
                ldsm4(ah[mt], sb + (aBase + off) * 2);
            }
            #pragma unroll
            for (int np = 0; np < 3; ++np) {
                uint32_t boff = (uint32_t)((wn * 48 + np * 16 + bN) * KS + kk + bK);
                uint32_t bh[4];
                ldsm4(bh, sb + (bBase + boff) * 2);
                #pragma unroll
                for (int mt = 0; mt < 2; ++mt)
                    #pragma unroll
                    for (int sub = 0; sub < 2; ++sub)
                        mma16816h(c[mt][sub + np * 2], ah[mt],
                                  bh[sub * 2], bh[sub * 2 + 1]);
            }
        }

        aCur[0] = aNxt[0];
        aCur[1] = aNxt[1];
        p ^= 1;
    }

    // ---- epilogue: fp32 acc -> single fp16 to g_h (q pre-scaled by 0.125)
    const int t4 = lane >> 2;
    const int c2 = (lane & 3) * 2;
    #pragma unroll
    for (int mt = 0; mt < 2; ++mt)
        #pragma unroll
        for (int nt = 0; nt < 6; ++nt) {
            int col = wn * 48 + nt * 8 + c2;
            int sel = col >> 6;
            int hc  = col & 63;
            float s = (sel == 0) ? 0.125f : 1.0f;
            size_t base = (size_t)sel * HEADELEMS +
                          (size_t)(m0 + wm * 32 + mt * 16 + t4) * HH + hc;
            *(uint32_t*)(g_h + base) =
                packhf(c[mt][nt][0] * s, c[mt][nt][1] * s);
            *(uint32_t*)(g_h + base + 8 * HH) =
                packhf(c[mt][nt][2] * s, c[mt][nt][3] * s);
        }
}

// ---------------------------------------------------------------------------
// Tensor-core flash attention, fp16 single-product GEMMs, 2 CTAs/SM.
// (unchanged from R10)
// ---------------------------------------------------------------------------
#define AST 72
#define Q_S 0
#define K_S (256*AST)
#define V_S (2*256*AST)
#define ATTN_SMEM (3*256*AST*2)    // 110592 bytes

__global__ void __launch_bounds__(256, 2) attn_mma_kernel(float* __restrict__ out)
{
    extern __shared__ __half asmem[];
    const uint32_t sb = smem_u32(asmem);
    const int b    = blockIdx.x;
    const int tid  = threadIdx.x;
    const int lane = tid & 31;
    const int w    = tid >> 5;
    const int t4   = lane >> 2;
    const int tg   = lane & 3;

    // ---- cp.async load: 3 arrays of [256][64] fp16 -> stride-72 smem
    #pragma unroll
    for (int it = 0; it < 24; ++it) {
        const int arr = it >> 3;               // 8 iterations per array
        int rem = (tid + it * 256) - arr * 2048;
        int r   = rem >> 3;
        int kg  = (rem & 7) * 8;
        const __half* src = g_h + (size_t)arr * HEADELEMS +
                            ((size_t)b * TT + r) * HH + kg;
        uint32_t dst = sb + (uint32_t)(arr * 256 * AST + r * AST + kg) * 2;
        cpasync16(dst, src);
    }
    asm volatile("cp.async.commit_group;\n\tcp.async.wait_group 0;" ::: "memory");
    __syncthreads();

    const int Rb[2] = { 16 * w, 240 - 16 * w };

    float o[2][8][4];
    float mrow[2][2], lrow[2][2];
    #pragma unroll
    for (int mt = 0; mt < 2; ++mt) {
        mrow[mt][0] = mrow[mt][1] = -1e30f;
        lrow[mt][0] = lrow[mt][1] = 0.f;
        #pragma unroll
        for (int nt = 0; nt < 8; ++nt)
            #pragma unroll
            for (int j = 0; j < 4; ++j) o[mt][nt][j] = 0.f;
    }

    const int qRow = lane & 15;
    const int qCol = ((lane >> 4) & 1) * 8;
    const int kRow = (lane & 7) + ((lane >> 4) & 1) * 8;
    const int kCol = ((lane >> 3) & 1) * 8;
    const int vRow = lane & 15;
    const int vCol = ((lane >> 4) & 1) * 8;

    #pragma unroll 1
    for (int s0 = 0; s0 < TT; s0 += 64) {
        #pragma unroll
        for (int mt = 0; mt < 2; ++mt) {
            const int base = Rb[mt];
            if (s0 > base + 15) continue;

            const int npMax = min(4, ((base + 15 - s0) >> 4) + 1);

            // ---- S = Q K^T (fp16, single product)
            float sc[8][4];
            #pragma unroll
            for (int nt = 0; nt < 8; ++nt)
                #pragma unroll
                for (int j = 0; j < 4; ++j) sc[nt][j] = 0.f;

            #pragma unroll
            for (int kc = 0; kc < 4; ++kc) {
                uint32_t qh[4];
                uint32_t qoff = (uint32_t)((base + qRow) * AST + kc * 16 + qCol);
                ldsm4(qh, sb + (Q_S + qoff) * 2);
                #pragma unroll
                for (int np = 0; np < 4; ++np) {
                    if (np < npMax) {
                        uint32_t koff = (uint32_t)((s0 + np * 16 + kRow) * AST + kc * 16 + kCol);
                        uint32_t kh[4];
                        ldsm4(kh, sb + (K_S + koff) * 2);
                        mma16816h(sc[2 * np],     qh, kh[0], kh[1]);
                        mma16816h(sc[2 * np + 1], qh, kh[2], kh[3]);
                    }
                }
            }

            // ---- causal mask + online softmax
            const int r0 = base + t4;
            const int r1 = r0 + 8;
            #pragma unroll
            for (int nt = 0; nt < 8; ++nt) {
                int col = s0 + 8 * nt + 2 * tg;
                if (col     > r0) sc[nt][0] = -1e30f;
                if (col + 1 > r0) sc[nt][1] = -1e30f;
                if (col     > r1) sc[nt][2] = -1e30f;
                if (col + 1 > r1) sc[nt][3] = -1e30f;
            }
            float mx0 = sc[0][0], mx1 = sc[0][2];
            #pragma unroll
            for (int nt = 0; nt < 8; ++nt) {
                mx0 = fmaxf(mx0, fmaxf(sc[nt][0], sc[nt][1]));
                mx1 = fmaxf(mx1, fmaxf(sc[nt][2], sc[nt][3]));
            }
            mx0 = fmaxf(mx0, __shfl_xor_sync(0xffffffffu, mx0, 1));
            mx0 = fmaxf(mx0, __shfl_xor_sync(0xffffffffu, mx0, 2));
            mx1 = fmaxf(mx1, __shfl_xor_sync(0xffffffffu, mx1, 1));
            mx1 = fmaxf(mx1, __shfl_xor_sync(0xffffffffu, mx1, 2));

            float nm0 = fmaxf(mrow[mt][0], mx0);
            float nm1 = fmaxf(mrow[mt][1], mx1);
            float corr0 = __expf(mrow[mt][0] - nm0);
            float corr1 = __expf(mrow[mt][1] - nm1);
            mrow[mt][0] = nm0;
            mrow[mt][1] = nm1;

            float sum0 = 0.f, sum1 = 0.f;
            #pragma unroll
            for (int nt = 0; nt < 8; ++nt) {
                sc[nt][0] = __expf(sc[nt][0] - nm0);
                sc[nt][1] = __expf(sc[nt][1] - nm0);
                sc[nt][2] = __expf(sc[nt][2] - nm1);
                sc[nt][3] = __expf(sc[nt][3] - nm1);
                sum0 += sc[nt][0] + sc[nt][1];
                sum1 += sc[nt][2] + sc[nt][3];
            }
            sum0 += __shfl_xor_sync(0xffffffffu, sum0, 1);
            sum0 += __shfl_xor_sync(0xffffffffu, sum0, 2);
            sum1 += __shfl_xor_sync(0xffffffffu, sum1, 1);
            sum1 += __shfl_xor_sync(0xffffffffu, sum1, 2);
            lrow[mt][0] = lrow[mt][0] * corr0 + sum0;
            lrow[mt][1] = lrow[mt][1] * corr1 + sum1;

            #pragma unroll
            for (int nt = 0; nt < 8; ++nt) {
                o[mt][nt][0] *= corr0;
                o[mt][nt][1] *= corr0;
                o[mt][nt][2] *= corr1;
                o[mt][nt][3] *= corr1;
            }

            // ---- O += P V (fp16, single product); skip zero tiles
            #pragma unroll
            for (int kv = 0; kv < 4; ++kv) {
                if (kv < npMax) {
                    uint32_t ph[4];
                    #pragma unroll
                    for (int half = 0; half < 2; ++half) {
                        const float* f = sc[2 * kv + half];
                        ph[2 * half]     = packhf(f[0], f[1]);
                        ph[2 * half + 1] = packhf(f[2], f[3]);
                    }
                    #pragma unroll
                    for (int np = 0; np < 4; ++np) {
                        uint32_t voff = (uint32_t)((s0 + kv * 16 + vRow) * AST + np * 16 + vCol);
                        uint32_t vh[4];
                        ldsm4t(vh, sb + (V_S + voff) * 2);
                        mma16816h(o[mt][2 * np],     ph, vh[0], vh[1]);
                        mma16816h(o[mt][2 * np + 1], ph, vh[2], vh[3]);
                    }
                }
            }
        }
    }

    // ---- write out
    #pragma unroll
    for (int mt = 0; mt < 2; ++mt) {
        const int r0 = Rb[mt] + t4;
        const float inv0 = 1.f / lrow[mt][0];
        const float inv1 = 1.f / lrow[mt][1];
        #pragma unroll
        for (int nt = 0; nt < 8; ++nt) {
            int col = 8 * nt + 2 * tg;
            size_t o0 = ((size_t)b * TT + r0) * HH + col;
            *(float2*)(out + o0)           = make_float2(o[mt][nt][0] * inv0,
                                                         o[mt][nt][1] * inv0);
            *(float2*)(out + o0 + 8 * HH)  = make_float2(o[mt][nt][2] * inv1,
                                                         o[mt][nt][3] * inv1);
        }
    }
}

// ---------------------------------------------------------------------------
extern "C" void kernel_launch(void* const* d_in, const int* in_sizes, int n_in,
                              void* d_out, int out_size)
{
    const float* x  = (const float*)d_in[0];
    const float* Wq = (const float*)d_in[1];
    const float* Wk = (const float*)d_in[2];
    const float* Wv = (const float*)d_in[3];
    float* out = (float*)d_out;

    cudaFuncSetAttribute(proj_mma_kernel,
                         cudaFuncAttributeMaxDynamicSharedMemorySize, PROJ_SMEM);
    cudaFuncSetAttribute(attn_mma_kernel,
                         cudaFuncAttributeMaxDynamicSharedMemorySize, ATTN_SMEM);

    wsplit_kernel<<<36, 256>>>(Wq, Wk, Wv);
    proj_mma_kernel<<<MTOT / 64, 256, PROJ_SMEM>>>(x);
    attn_mma_kernel<<<BB, 256, ATTN_SMEM>>>(out);
}

// round 12
// speedup vs baseline: 4.5327x; 1.0551x over previous
#include <cuda_runtime.h>
#include <cuda_fp16.h>
#include <math.h>
#include <stdint.h>

#define BB   256
#define TT   256
#define DD   384
#define HH   64
#define MTOT (BB*TT)                       // 65536 rows
#define HEADELEMS ((size_t)MTOT*HH)

// scratch: q,k,v fp16 (attn operands) + transposed fp16 weights (proj)
__device__ __half g_h[3 * (size_t)MTOT * HH];
__device__ __half g_wh[192 * 384];

// ---------------------------------------------------------------------------
__device__ __forceinline__ uint32_t smem_u32(const void* p) {
    uint32_t a;
    asm("{ .reg .u64 t; cvta.to.shared.u64 t, %1; cvt.u32.u64 %0, t; }"
        : "=r"(a) : "l"(p));
    return a;
}

__device__ __forceinline__ void ldsm4(uint32_t r[4], uint32_t addr) {
    asm volatile("ldmatrix.sync.aligned.m8n8.x4.shared.b16 {%0,%1,%2,%3}, [%4];"
                 : "=r"(r[0]), "=r"(r[1]), "=r"(r[2]), "=r"(r[3]) : "r"(addr));
}

__device__ __forceinline__ void ldsm4t(uint32_t r[4], uint32_t addr) {
    asm volatile("ldmatrix.sync.aligned.m8n8.x4.trans.shared.b16 {%0,%1,%2,%3}, [%4];"
                 : "=r"(r[0]), "=r"(r[1]), "=r"(r[2]), "=r"(r[3]) : "r"(addr));
}

// fp16 mma
__device__ __forceinline__ void mma16816h(float c[4], const uint32_t a[4],
                                          uint32_t b0, uint32_t b1) {
    asm volatile(
        "mma.sync.aligned.m16n8k16.row.col.f32.f16.f16.f32 "
        "{%0,%1,%2,%3}, {%4,%5,%6,%7}, {%8,%9}, {%0,%1,%2,%3};"
        : "+f"(c[0]), "+f"(c[1]), "+f"(c[2]), "+f"(c[3])
        : "r"(a[0]), "r"(a[1]), "r"(a[2]), "r"(a[3]), "r"(b0), "r"(b1));
}

// pack two f32 -> f16x2 (first arg in low half)
__device__ __forceinline__ uint32_t packhf(float lo, float hi) {
    __half2 h = __floats2half2_rn(lo, hi);
    return *(uint32_t*)&h;
}

__device__ __forceinline__ void cpasync16(uint32_t dst, const void* src) {
    asm volatile("cp.async.cg.shared.global [%0], [%1], 16;"
                 :: "r"(dst), "l"(src));
}

// ---------------------------------------------------------------------------
// Weight prep: smem-tiled transpose, single fp16.
// ---------------------------------------------------------------------------
__global__ void wsplit_kernel(const float* __restrict__ Wq,
                              const float* __restrict__ Wk,
                              const float* __restrict__ Wv) {
    __shared__ float ws[32][65];
    const int sel = blockIdx.x / 12;
    const int k0  = (blockIdx.x % 12) * 32;
    const float* W = (sel == 0) ? Wq : (sel == 1) ? Wk : Wv;
    const int tid = threadIdx.x;

    #pragma unroll
    for (int it = 0; it < 8; ++it) {
        int idx = tid + it * 256;          // 0..2047
        int k = idx >> 6, n = idx & 63;
        ws[k][n] = W[(size_t)(k0 + k) * HH + n];
    }
    __syncthreads();
    #pragma unroll
    for (int it = 0; it < 8; ++it) {
        int idx = tid + it * 256;
        int n = idx >> 5, k = idx & 31;
        g_wh[(size_t)(sel * 64 + n) * DD + k0 + k] = __float2half_rn(ws[k][n]);
    }
}

// ---------------------------------------------------------------------------
// Deep-pipelined fp16 single-product projection: D = xh*wh.
// B: 4-stage cp.async ring, wait_group 2 (2 chunks in flight).
// A: LDG issued 2 chunks ahead (3 register stages), STS into 2-stage smem.
// ---------------------------------------------------------------------------
#define KC    32
#define KS    40
#define ABUFH 2560     // halves: 64*40 per A stage (x2)
#define B_BASE 5120    // halves
#define BBUFH 7680     // halves: 192*40 per B stage (x4)
#define PROJ_SMEM ((5120 + 4 * 7680) * 2)   // 71680 bytes

__global__ void __launch_bounds__(256, 2) proj_mma_kernel(const float* __restrict__ x)
{
    extern __shared__ __half sm[];
    const uint32_t sb = smem_u32(sm);
    const int tid  = threadIdx.x;
    const int lane = tid & 31;
    const int wid  = tid >> 5;
    const int wm   = wid & 1;
    const int wn   = wid >> 1;
    const int m0   = blockIdx.x * 64;

    const int aRow = (lane & 7) + ((lane >> 3) & 1) * 8;
    const int aCol = ((lane >> 4) & 1) * 8;
    const int bN   = (lane & 7) + ((lane >> 4) & 1) * 8;
    const int bK   = ((lane >> 3) & 1) * 8;

    // per-thread load geometry
    const int bn = tid >> 2;            // B row 0..191 (768 threads-worth over 3 its)
    const int an = tid >> 3;            // A row (it=0)

    float c[2][6][4];
    #pragma unroll
    for (int mt = 0; mt < 2; ++mt)
        #pragma unroll
        for (int nt = 0; nt < 6; ++nt)
            #pragma unroll
            for (int j = 0; j < 4; ++j) c[mt][nt][j] = 0.f;

    float4 a0[2], a1[2], a2[2];

    // ---- prologue: B(0), B(1) cp.async (groups 0,1); A(0), A(1) LDG
    #pragma unroll
    for (int s = 0; s < 2; ++s) {
        #pragma unroll
        for (int it = 0; it < 3; ++it) {
            int idx = tid + it * 256;              // 0..767
            int n   = idx >> 2;
            int kg  = (idx & 3) * 8;
            cpasync16(sb + (uint32_t)(B_BASE + s * BBUFH + n * KS + kg) * 2,
                      g_wh + (size_t)n * DD + s * KC + kg);
        }
        asm volatile("cp.async.commit_group;" ::: "memory");
    }
    #pragma unroll
    for (int it = 0; it < 2; ++it) {
        int idx = tid + it * 256;
        int r = idx >> 3, c4 = (idx & 7) * 4;
        a0[it] = *(const float4*)(x + (size_t)(m0 + r) * DD + c4);
        a1[it] = *(const float4*)(x + (size_t)(m0 + r) * DD + KC + c4);
    }

    #pragma unroll 1
    for (int ch = 0; ch < 12; ++ch) {
        // ---- issue B(ch+2) + LDG A(ch+2) (2 chunks ahead)
        if (ch < 10) {
            const int k2 = (ch + 2) * KC;
            #pragma unroll
            for (int it = 0; it < 3; ++it) {
                int idx = tid + it * 256;
                int n   = idx >> 2;
                int kg  = (idx & 3) * 8;
                cpasync16(sb + (uint32_t)(B_BASE + ((ch + 2) & 3) * BBUFH +
                                          n * KS + kg) * 2,
                          g_wh + (size_t)n * DD + k2 + kg);
            }
            asm volatile("cp.async.commit_group;" ::: "memory");
            #pragma unroll
            for (int it = 0; it < 2; ++it) {
                int idx = tid + it * 256;
                int r = idx >> 3, c4 = (idx & 7) * 4;
                a2[it] = *(const float4*)(x + (size_t)(m0 + r) * DD + k2 + c4);
            }
        } else {
            asm volatile("cp.async.commit_group;" ::: "memory");   // empty group
        }

        // ---- STS A(ch) (convert fp32 -> fp16)
        #pragma unroll
        for (int it = 0; it < 2; ++it) {
            int idx = tid + it * 256;
            int r = idx >> 3, c4 = (idx & 7) * 4;
            float4 v = a0[it];
            int off = (ch & 1) * ABUFH + r * KS + c4;
            *(uint2*)(sm + off) = make_uint2(packhf(v.x, v.y), packhf(v.z, v.w));
        }

        // ---- B(ch) guaranteed complete with 2 groups still in flight
        asm volatile("cp.async.wait_group 2;" ::: "memory");
        __syncthreads();

        // ---- MMA over stage buffers
        const uint32_t aBase = (uint32_t)((ch & 1) * ABUFH);
        const uint32_t bBase = (uint32_t)(B_BASE + (ch & 3) * BBUFH);
        #pragma unroll
        for (int ks = 0; ks < 2; ++ks) {
            const int kk = ks * 16;
            uint32_t ah[2][4];
            #pragma unroll
            for (int mt = 0; mt < 2; ++mt) {
                uint32_t off = (uint32_t)((wm * 32 + mt * 16 + aRow) * KS + kk + aCol);
                ldsm4(ah[mt], sb + (aBase + off) * 2);
            }
            #pragma unroll
            for (int np = 0; np < 3; ++np) {
                uint32_t boff = (uint32_t)((wn * 48 + np * 16 + bN) * KS + kk + bK);
                uint32_t bh[4];
                ldsm4(bh, sb + (bBase + boff) * 2);
                #pragma unroll
                for (int mt = 0; mt < 2; ++mt)
                    #pragma unroll
                    for (int sub = 0; sub < 2; ++sub)
                        mma16816h(c[mt][sub + np * 2], ah[mt],
                                  bh[sub * 2], bh[sub * 2 + 1]);
            }
        }

        a0[0] = a1[0]; a0[1] = a1[1];
        a1[0] = a2[0]; a1[1] = a2[1];
    }

    // ---- epilogue: fp32 acc -> single fp16 to g_h (q pre-scaled by 0.125)
    const int t4 = lane >> 2;
    const int c2 = (lane & 3) * 2;
    #pragma unroll
    for (int mt = 0; mt < 2; ++mt)
        #pragma unroll
        for (int nt = 0; nt < 6; ++nt) {
            int col = wn * 48 + nt * 8 + c2;
            int sel = col >> 6;
            int hc  = col & 63;
            float s = (sel == 0) ? 0.125f : 1.0f;
            size_t base = (size_t)sel * HEADELEMS +
                          (size_t)(m0 + wm * 32 + mt * 16 + t4) * HH + hc;
            *(uint32_t*)(g_h + base) =
                packhf(c[mt][nt][0] * s, c[mt][nt][1] * s);
            *(uint32_t*)(g_h + base + 8 * HH) =
                packhf(c[mt][nt][2] * s, c[mt][nt][3] * s);
        }
}

// ---------------------------------------------------------------------------
// Tensor-core flash attention, fp16 single-product GEMMs, 2 CTAs/SM.
// (unchanged from R11)
// ---------------------------------------------------------------------------
#define AST 72
#define Q_S 0
#define K_S (256*AST)
#define V_S (2*256*AST)
#define ATTN_SMEM (3*256*AST*2)    // 110592 bytes

__global__ void __launch_bounds__(256, 2) attn_mma_kernel(float* __restrict__ out)
{
    extern __shared__ __half asmem[];
    const uint32_t sb = smem_u32(asmem);
    const int b    = blockIdx.x;
    const int tid  = threadIdx.x;
    const int lane = tid & 31;
    const int w    = tid >> 5;
    const int t4   = lane >> 2;
    const int tg   = lane & 3;

    // ---- cp.async load: 3 arrays of [256][64] fp16 -> stride-72 smem
    #pragma unroll
    for (int it = 0; it < 24; ++it) {
        const int arr = it >> 3;               // 8 iterations per array
        int rem = (tid + it * 256) - arr * 2048;
        int r   = rem >> 3;
        int kg  = (rem & 7) * 8;
        const __half* src = g_h + (size_t)arr * HEADELEMS +
                            ((size_t)b * TT + r) * HH + kg;
        uint32_t dst = sb + (uint32_t)(arr * 256 * AST + r * AST + kg) * 2;
        cpasync16(dst, src);
    }
    asm volatile("cp.async.commit_group;\n\tcp.async.wait_group 0;" ::: "memory");
    __syncthreads();

    const int Rb[2] = { 16 * w, 240 - 16 * w };

    float o[2][8][4];
    float mrow[2][2], lrow[2][2];
    #pragma unroll
    for (int mt = 0; mt < 2; ++mt) {
        mrow[mt][0] = mrow[mt][1] = -1e30f;
        lrow[mt][0] = lrow[mt][1] = 0.f;
        #pragma unroll
        for (int nt = 0; nt < 8; ++nt)
            #pragma unroll
            for (int j = 0; j < 4; ++j) o[mt][nt][j] = 0.f;
    }

    const int qRow = lane & 15;
    const int qCol = ((lane >> 4) & 1) * 8;
    const int kRow = (lane & 7) + ((lane >> 4) & 1) * 8;
    const int kCol = ((lane >> 3) & 1) * 8;
    const int vRow = lane & 15;
    const int vCol = ((lane >> 4) & 1) * 8;

    #pragma unroll 1
    for (int s0 = 0; s0 < TT; s0 += 64) {
        #pragma unroll
        for (int mt = 0; mt < 2; ++mt) {
            const int base = Rb[mt];
            if (s0 > base + 15) continue;

            const int npMax = min(4, ((base + 15 - s0) >> 4) + 1);

            // ---- S = Q K^T (fp16, single product)
            float sc[8][4];
            #pragma unroll
            for (int nt = 0; nt < 8; ++nt)
                #pragma unroll
                for (int j = 0; j < 4; ++j) sc[nt][j] = 0.f;

            #pragma unroll
            for (int kc = 0; kc < 4; ++kc) {
                uint32_t qh[4];
                uint32_t qoff = (uint32_t)((base + qRow) * AST + kc * 16 + qCol);
                ldsm4(qh, sb + (Q_S + qoff) * 2);
                #pragma unroll
                for (int np = 0; np < 4; ++np) {
                    if (np < npMax) {
                        uint32_t koff = (uint32_t)((s0 + np * 16 + kRow) * AST + kc * 16 + kCol);
                        uint32_t kh[4];
                        ldsm4(kh, sb + (K_S + koff) * 2);
                        mma16816h(sc[2 * np],     qh, kh[0], kh[1]);
                        mma16816h(sc[2 * np + 1], qh, kh[2], kh[3]);
                    }
                }
            }

            // ---- causal mask + online softmax
            const int r0 = base + t4;
            const int r1 = r0 + 8;
            #pragma unroll
            for (int nt = 0; nt < 8; ++nt) {
                int col = s0 + 8 * nt + 2 * tg;
                if (col     > r0) sc[nt][0] = -1e30f;
                if (col + 1 > r0) sc[nt][1] = -1e30f;
                if (col     > r1) sc[nt][2] = -1e30f;
                if (col + 1 > r1) sc[nt][3] = -1e30f;
            }
            float mx0 = sc[0][0], mx1 = sc[0][2];
            #pragma unroll
            for (int nt = 0; nt < 8; ++nt) {
                mx0 = fmaxf(mx0, fmaxf(sc[nt][0], sc[nt][1]));
                mx1 = fmaxf(mx1, fmaxf(sc[nt][2], sc[nt][3]));
            }
            mx0 = fmaxf(mx0, __shfl_xor_sync(0xffffffffu, mx0, 1));
            mx0 = fmaxf(mx0, __shfl_xor_sync(0xffffffffu, mx0, 2));
            mx1 = fmaxf(mx1, __shfl_xor_sync(0xffffffffu, mx1, 1));
            mx1 = fmaxf(mx1, __shfl_xor_sync(0xffffffffu, mx1, 2));

            float nm0 = fmaxf(mrow[mt][0], mx0);
            float nm1 = fmaxf(mrow[mt][1], mx1);
            float corr0 = __expf(mrow[mt][0] - nm0);
            float corr1 = __expf(mrow[mt][1] - nm1);
            mrow[mt][0] = nm0;
            mrow[mt][1] = nm1;

            float sum0 = 0.f, sum1 = 0.f;
            #pragma unroll
            for (int nt = 0; nt < 8; ++nt) {
                sc[nt][0] = __expf(sc[nt][0] - nm0);
                sc[nt][1] = __expf(sc[nt][1] - nm0);
                sc[nt][2] = __expf(sc[nt][2] - nm1);
                sc[nt][3] = __expf(sc[nt][3] - nm1);
                sum0 += sc[nt][0] + sc[nt][1];
                sum1 += sc[nt][2] + sc[nt][3];
            }
            sum0 += __shfl_xor_sync(0xffffffffu, sum0, 1);
            sum0 += __shfl_xor_sync(0xffffffffu, sum0, 2);
            sum1 += __shfl_xor_sync(0xffffffffu, sum1, 1);
            sum1 += __shfl_xor_sync(0xffffffffu, sum1, 2);
            lrow[mt][0] = lrow[mt][0] * corr0 + sum0;
            lrow[mt][1] = lrow[mt][1] * corr1 + sum1;

            #pragma unroll
            for (int nt = 0; nt < 8; ++nt) {
                o[mt][nt][0] *= corr0;
                o[mt][nt][1] *= corr0;
                o[mt][nt][2] *= corr1;
                o[mt][nt][3] *= corr1;
            }

            // ---- O += P V (fp16, single product); skip zero tiles
            #pragma unroll
            for (int kv = 0; kv < 4; ++kv) {
                if (kv < npMax) {
                    uint32_t ph[4];
                    #pragma unroll
                    for (int half = 0; half < 2; ++half) {
                        const float* f = sc[2 * kv + half];
                        ph[2 * half]     = packhf(f[0], f[1]);
                        ph[2 * half + 1] = packhf(f[2], f[3]);
                    }
                    #pragma unroll
                    for (int np = 0; np < 4; ++np) {
                        uint32_t voff = (uint32_t)((s0 + kv * 16 + vRow) * AST + np * 16 + vCol);
                        uint32_t vh[4];
                        ldsm4t(vh, sb + (V_S + voff) * 2);
                        mma16816h(o[mt][2 * np],     ph, vh[0], vh[1]);
                        mma16816h(o[mt][2 * np + 1], ph, vh[2], vh[3]);
                    }
                }
            }
        }
    }

    // ---- write out
    #pragma unroll
    for (int mt = 0; mt < 2; ++mt) {
        const int r0 = Rb[mt] + t4;
        const float inv0 = 1.f / lrow[mt][0];
        const float inv1 = 1.f / lrow[mt][1];
        #pragma unroll
        for (int nt = 0; nt < 8; ++nt) {
            int col = 8 * nt + 2 * tg;
            size_t o0 = ((size_t)b * TT + r0) * HH + col;
            *(float2*)(out + o0)           = make_float2(o[mt][nt][0] * inv0,
                                                         o[mt][nt][1] * inv0);
            *(float2*)(out + o0 + 8 * HH)  = make_float2(o[mt][nt][2] * inv1,
                                                         o[mt][nt][3] * inv1);
        }
    }
}

// ---------------------------------------------------------------------------
extern "C" void kernel_launch(void* const* d_in, const int* in_sizes, int n_in,
                              void* d_out, int out_size)
{
    const float* x  = (const float*)d_in[0];
    const float* Wq = (const float*)d_in[1];
    const float* Wk = (const float*)d_in[2];
    const float* Wv = (const float*)d_in[3];
    float* out = (float*)d_out;

    cudaFuncSetAttribute(proj_mma_kernel,
                         cudaFuncAttributeMaxDynamicSharedMemorySize, PROJ_SMEM);
    cudaFuncSetAttribute(attn_mma_kernel,
                         cudaFuncAttributeMaxDynamicSharedMemorySize, ATTN_SMEM);

    wsplit_kernel<<<36, 256>>>(Wq, Wk, Wv);
    proj_mma_kernel<<<MTOT / 64, 256, PROJ_SMEM>>>(x);
    attn_mma_kernel<<<BB, 256, ATTN_SMEM>>>(out);
}